// round 3
// baseline (speedup 1.0000x reference)
#include <cuda_runtime.h>
#include <cuda_bf16.h>
#include <math.h>
#include <stdint.h>

#define SEQ    2048
#define NROWS  4096
#define NHEADS 16

// ---------------- scratch ----------------
__device__ float g_q1 [NROWS * 512];
__device__ float g_q  [NROWS * 3072];
__device__ float g_ckv[NROWS * 576];
__device__ float g_kv [NROWS * 4096];
__device__ float g_att[NROWS * 2048];

// ================= helpers =================
__device__ __forceinline__ uint32_t smem_u32(const void* p) {
    uint32_t a;
    asm("{ .reg .u64 t; cvta.to.shared.u64 t, %1; cvt.u32.u64 %0, t; }" : "=r"(a) : "l"(p));
    return a;
}
__device__ __forceinline__ void ldsm4(uint32_t& r0, uint32_t& r1, uint32_t& r2, uint32_t& r3,
                                      uint32_t addr) {
    asm volatile("ldmatrix.sync.aligned.m8n8.x4.shared.b16 {%0,%1,%2,%3}, [%4];"
                 : "=r"(r0), "=r"(r1), "=r"(r2), "=r"(r3) : "r"(addr));
}
__device__ __forceinline__ void ldsm2t(uint32_t& r0, uint32_t& r1, uint32_t addr) {
    asm volatile("ldmatrix.sync.aligned.m8n8.x2.trans.shared.b16 {%0,%1}, [%2];"
                 : "=r"(r0), "=r"(r1) : "r"(addr));
}
__device__ __forceinline__ void mma16816(float* c, const uint32_t* a, const uint32_t* b) {
    asm volatile(
        "mma.sync.aligned.m16n8k16.row.col.f32.bf16.bf16.f32 "
        "{%0,%1,%2,%3}, {%4,%5,%6,%7}, {%8,%9}, {%0,%1,%2,%3};"
        : "+f"(c[0]), "+f"(c[1]), "+f"(c[2]), "+f"(c[3])
        : "r"(a[0]), "r"(a[1]), "r"(a[2]), "r"(a[3]), "r"(b[0]), "r"(b[1]));
}
__device__ __forceinline__ uint32_t pack_bf2(__nv_bfloat16 a, __nv_bfloat16 b) {
    __nv_bfloat162 t(a, b);
    return *reinterpret_cast<uint32_t*>(&t);
}
__device__ __forceinline__ void cvt_split4(float4 v, uint2& hi, uint2& lo) {
    __nv_bfloat16 h0 = __float2bfloat16(v.x), h1 = __float2bfloat16(v.y),
                  h2 = __float2bfloat16(v.z), h3 = __float2bfloat16(v.w);
    __nv_bfloat16 l0 = __float2bfloat16(v.x - __bfloat162float(h0)),
                  l1 = __float2bfloat16(v.y - __bfloat162float(h1)),
                  l2 = __float2bfloat16(v.z - __bfloat162float(h2)),
                  l3 = __float2bfloat16(v.w - __bfloat162float(h3));
    hi.x = pack_bf2(h0, h1); hi.y = pack_bf2(h2, h3);
    lo.x = pack_bf2(l0, l1); lo.y = pack_bf2(l2, l3);
}

// ================= HMMA bf16-split GEMM: C[M,N] = A[M,K] @ B[K,N] (fp32 in/out) ==========
// CTA: 128(M) x 64(N), K-chunk 64, 256 threads (8 warps, each 32x32).
// Requires M%128==0, N%64==0, K%64==0.
#define ALD 72          // A smem row stride (bf16 elems)
#define BLD 72          // B smem row stride
#define SM_AH 0
#define SM_AL (128 * ALD)
#define SM_BH (2 * 128 * ALD)
#define SM_BL (2 * 128 * ALD + 64 * BLD)
#define GEMM_SMEM ((2 * 128 * ALD + 2 * 64 * BLD) * 2)   // bytes = 55296

__global__ __launch_bounds__(256) void gemm_hmma(
    const float* __restrict__ A, int lda,
    const float* __restrict__ B, int ldb,
    float* __restrict__ C, int ldc,
    int nchunks)
{
    extern __shared__ __nv_bfloat16 sm[];
    const int tid  = threadIdx.x;
    const int wid  = tid >> 5;
    const int lane = tid & 31;
    const int m0 = blockIdx.y * 128;
    const int n0 = blockIdx.x * 64;
    const int mw = (wid & 3) * 32;       // warp m offset in CTA tile
    const int nw = (wid >> 2) * 32;      // warp n offset

    float acc[2][4][4];
    #pragma unroll
    for (int i = 0; i < 2; i++)
        #pragma unroll
        for (int j = 0; j < 4; j++)
            #pragma unroll
            for (int e = 0; e < 4; e++) acc[i][j][e] = 0.f;

    // precomputed ldmatrix base addresses (byte smem addresses)
    const uint32_t aRow = (lane & 15);
    const uint32_t aCol = (lane >> 4) * 8;
    const uint32_t sm_base = smem_u32(sm);
    const uint32_t aHiBase = sm_base + (SM_AH + (mw + aRow) * ALD + aCol) * 2;
    const uint32_t aLoBase = sm_base + (SM_AL + (mw + aRow) * ALD + aCol) * 2;
    const uint32_t bHiBase = sm_base + (SM_BH + (lane & 15) * BLD + nw) * 2;
    const uint32_t bLoBase = sm_base + (SM_BL + (lane & 15) * BLD + nw) * 2;

    for (int ch = 0; ch < nchunks; ch++) {
        const int k0 = ch * 64;

        // ---- stage A [128 m][64 k] hi/lo ----
        #pragma unroll 2
        for (int i = tid; i < 128 * 16; i += 256) {
            int r = i >> 4, c4 = i & 15;
            float4 v = *reinterpret_cast<const float4*>(A + (size_t)(m0 + r) * lda + k0 + c4 * 4);
            uint2 hi, lo; cvt_split4(v, hi, lo);
            *reinterpret_cast<uint2*>(sm + SM_AH + r * ALD + c4 * 4) = hi;
            *reinterpret_cast<uint2*>(sm + SM_AL + r * ALD + c4 * 4) = lo;
        }
        // ---- stage B [64 k][64 n] hi/lo (as-is, row-major over k) ----
        #pragma unroll 2
        for (int i = tid; i < 64 * 16; i += 256) {
            int kr = i >> 4, nc4 = i & 15;
            float4 v = *reinterpret_cast<const float4*>(B + (size_t)(k0 + kr) * ldb + n0 + nc4 * 4);
            uint2 hi, lo; cvt_split4(v, hi, lo);
            *reinterpret_cast<uint2*>(sm + SM_BH + kr * BLD + nc4 * 4) = hi;
            *reinterpret_cast<uint2*>(sm + SM_BL + kr * BLD + nc4 * 4) = lo;
        }
        __syncthreads();

        // ---- compute: 4 k-steps of m16n8k16, 3 split passes ----
        #pragma unroll
        for (int ks = 0; ks < 4; ks++) {
            const uint32_t kOffA = (uint32_t)(ks * 16) * 2;          // A: +16 elems along k
            const uint32_t kOffB = (uint32_t)(ks * 16 * BLD) * 2;    // B: +16 rows
            uint32_t aH[2][4], aL[2][4], bH[4][2], bL[4][2];
            #pragma unroll
            for (int mi = 0; mi < 2; mi++) {
                uint32_t off = (uint32_t)(mi * 16 * ALD) * 2 + kOffA;
                ldsm4(aH[mi][0], aH[mi][1], aH[mi][2], aH[mi][3], aHiBase + off);
                ldsm4(aL[mi][0], aL[mi][1], aL[mi][2], aL[mi][3], aLoBase + off);
            }
            #pragma unroll
            for (int ni = 0; ni < 4; ni++) {
                uint32_t off = kOffB + (uint32_t)(ni * 8) * 2;
                ldsm2t(bH[ni][0], bH[ni][1], bHiBase + off);
                ldsm2t(bL[ni][0], bL[ni][1], bLoBase + off);
            }
            #pragma unroll
            for (int mi = 0; mi < 2; mi++)
                #pragma unroll
                for (int ni = 0; ni < 4; ni++) {
                    mma16816(acc[mi][ni], aH[mi], bH[ni]);
                    mma16816(acc[mi][ni], aH[mi], bL[ni]);
                    mma16816(acc[mi][ni], aL[mi], bH[ni]);
                }
        }
        __syncthreads();
    }

    // ---- epilogue: direct register -> global ----
    const int cr = lane >> 2;
    const int cc = (lane & 3) * 2;
    #pragma unroll
    for (int mi = 0; mi < 2; mi++)
        #pragma unroll
        for (int ni = 0; ni < 4; ni++) {
            int row = m0 + mw + mi * 16 + cr;
            int col = n0 + nw + ni * 8 + cc;
            *reinterpret_cast<float2*>(C + (size_t)row * ldc + col) =
                make_float2(acc[mi][ni][0], acc[mi][ni][1]);
            *reinterpret_cast<float2*>(C + (size_t)(row + 8) * ldc + col) =
                make_float2(acc[mi][ni][2], acc[mi][ni][3]);
        }
}

// ---------------- RoPE (fp32) ----------------
__global__ void rope_kernel()
{
    const int row  = blockIdx.x;
    const int pos  = row & (SEQ - 1);
    const int warp = threadIdx.x >> 5;
    const int lane = threadIdx.x & 31;

    float theta = __powf(10000.0f, -(float)lane * (1.0f / 32.0f));
    float ang = (float)pos * theta;
    float s, c;
    sincosf(ang, &s, &c);

    float* p;
    if (warp < 16)
        p = g_q + (size_t)row * 3072 + warp * 192 + 128 + 2 * lane;
    else
        p = g_ckv + (size_t)row * 576 + 512 + 2 * lane;

    float x1 = p[0], x2 = p[1];
    p[0] = x1 * c - x2 * s;
    p[1] = x1 * s + x2 * c;
}

// ---------------- flash attention (fp32 SIMT) ----------------
#define QS_LD 196
#define KS_LD 196
#define VS_LD 132
#define PS_LD 33
#define SMEM_ATTN ((64 * QS_LD + 32 * KS_LD + 32 * VS_LD + 64 * PS_LD) * 4)

__global__ __launch_bounds__(256, 1) void attn_kernel()
{
    extern __shared__ float smf[];
    float* Qs = smf;
    float* Ks = Qs + 64 * QS_LD;
    float* Vs = Ks + 32 * KS_LD;
    float* Ps = Vs + 32 * VS_LD;

    const int b = blockIdx.z, h = blockIdx.y;
    const int q0 = blockIdx.x * 64;
    const int tid = threadIdx.x;
    const int g = tid >> 3;
    const int c = tid & 7;
    const float scale = 0.07216878364870323f;

    for (int i = tid; i < 64 * 48; i += 256) {
        int r = i / 48, d4 = i - r * 48;
        float4 v = reinterpret_cast<const float4*>(
            g_q + (size_t)(b * SEQ + q0 + r) * 3072 + h * 192)[d4];
        reinterpret_cast<float4*>(Qs + r * QS_LD)[d4] = v;
    }

    const int qrow0 = q0 + 2 * g;
    const int qrow1 = qrow0 + 1;

    float m0 = -INFINITY, m1 = -INFINITY, l0 = 0.f, l1 = 0.f;
    float acc0[16], acc1[16];
    #pragma unroll
    for (int i = 0; i < 16; i++) { acc0[i] = 0.f; acc1[i] = 0.f; }

    for (int k0 = 0; k0 < q0 + 64; k0 += 32) {
        for (int i = tid; i < 32 * 32; i += 256) {
            int r = i >> 5, d4 = i & 31;
            reinterpret_cast<float4*>(Ks + r * KS_LD)[d4] =
                reinterpret_cast<const float4*>(
                    g_kv + (size_t)(b * SEQ + k0 + r) * 4096 + h * 256)[d4];
        }
        for (int i = tid; i < 32 * 16; i += 256) {
            int r = i >> 4, d4 = i & 15;
            reinterpret_cast<float4*>(Ks + r * KS_LD + 128)[d4] =
                reinterpret_cast<const float4*>(
                    g_ckv + (size_t)(b * SEQ + k0 + r) * 576 + 512)[d4];
        }
        for (int i = tid; i < 32 * 32; i += 256) {
            int r = i >> 5, d4 = i & 31;
            reinterpret_cast<float4*>(Vs + r * VS_LD)[d4] =
                reinterpret_cast<const float4*>(
                    g_kv + (size_t)(b * SEQ + k0 + r) * 4096 + h * 256 + 128)[d4];
        }
        __syncthreads();

        float sA[4] = {0, 0, 0, 0}, sB[4] = {0, 0, 0, 0};
        const float4* qp0 = reinterpret_cast<const float4*>(Qs + (2 * g)     * QS_LD);
        const float4* qp1 = reinterpret_cast<const float4*>(Qs + (2 * g + 1) * QS_LD);
        const float4* kp0 = reinterpret_cast<const float4*>(Ks + (c * 4 + 0) * KS_LD);
        const float4* kp1 = reinterpret_cast<const float4*>(Ks + (c * 4 + 1) * KS_LD);
        const float4* kp2 = reinterpret_cast<const float4*>(Ks + (c * 4 + 2) * KS_LD);
        const float4* kp3 = reinterpret_cast<const float4*>(Ks + (c * 4 + 3) * KS_LD);
        #pragma unroll 8
        for (int d4 = 0; d4 < 48; d4++) {
            float4 qa = qp0[d4], qb = qp1[d4];
            float4 k;
            k = kp0[d4];
            sA[0] += qa.x*k.x + qa.y*k.y + qa.z*k.z + qa.w*k.w;
            sB[0] += qb.x*k.x + qb.y*k.y + qb.z*k.z + qb.w*k.w;
            k = kp1[d4];
            sA[1] += qa.x*k.x + qa.y*k.y + qa.z*k.z + qa.w*k.w;
            sB[1] += qb.x*k.x + qb.y*k.y + qb.z*k.z + qb.w*k.w;
            k = kp2[d4];
            sA[2] += qa.x*k.x + qa.y*k.y + qa.z*k.z + qa.w*k.w;
            sB[2] += qb.x*k.x + qb.y*k.y + qb.z*k.z + qb.w*k.w;
            k = kp3[d4];
            sA[3] += qa.x*k.x + qa.y*k.y + qa.z*k.z + qa.w*k.w;
            sB[3] += qb.x*k.x + qb.y*k.y + qb.z*k.z + qb.w*k.w;
        }

        #pragma unroll
        for (int j = 0; j < 4; j++) {
            int kidx = k0 + c * 4 + j;
            sA[j] = (kidx <= qrow0) ? sA[j] * scale : -INFINITY;
            sB[j] = (kidx <= qrow1) ? sB[j] * scale : -INFINITY;
        }

        float t0 = fmaxf(fmaxf(sA[0], sA[1]), fmaxf(sA[2], sA[3]));
        float t1 = fmaxf(fmaxf(sB[0], sB[1]), fmaxf(sB[2], sB[3]));
        #pragma unroll
        for (int off = 1; off < 8; off <<= 1) {
            t0 = fmaxf(t0, __shfl_xor_sync(0xffffffffu, t0, off));
            t1 = fmaxf(t1, __shfl_xor_sync(0xffffffffu, t1, off));
        }
        float mn0 = fmaxf(m0, t0), mn1 = fmaxf(m1, t1);
        float a0 = expf(m0 - mn0), a1 = expf(m1 - mn1);
        m0 = mn0; m1 = mn1;

        float pA[4], pB[4];
        float ps0 = 0.f, ps1 = 0.f;
        #pragma unroll
        for (int j = 0; j < 4; j++) {
            pA[j] = expf(sA[j] - m0); ps0 += pA[j];
            pB[j] = expf(sB[j] - m1); ps1 += pB[j];
        }
        #pragma unroll
        for (int off = 1; off < 8; off <<= 1) {
            ps0 += __shfl_xor_sync(0xffffffffu, ps0, off);
            ps1 += __shfl_xor_sync(0xffffffffu, ps1, off);
        }
        l0 = l0 * a0 + ps0;
        l1 = l1 * a1 + ps1;

        #pragma unroll
        for (int j = 0; j < 4; j++) {
            Ps[(2 * g)     * PS_LD + c * 4 + j] = pA[j];
            Ps[(2 * g + 1) * PS_LD + c * 4 + j] = pB[j];
        }
        #pragma unroll
        for (int i = 0; i < 16; i++) { acc0[i] *= a0; acc1[i] *= a1; }
        __syncthreads();

        const float* pr0 = Ps + (2 * g)     * PS_LD;
        const float* pr1 = Ps + (2 * g + 1) * PS_LD;
        #pragma unroll 4
        for (int j = 0; j < 32; j++) {
            float p0 = pr0[j], p1 = pr1[j];
            const float4* vr = reinterpret_cast<const float4*>(Vs + j * VS_LD + c * 16);
            #pragma unroll
            for (int i4 = 0; i4 < 4; i4++) {
                float4 v = vr[i4];
                acc0[i4 * 4 + 0] += p0 * v.x; acc0[i4 * 4 + 1] += p0 * v.y;
                acc0[i4 * 4 + 2] += p0 * v.z; acc0[i4 * 4 + 3] += p0 * v.w;
                acc1[i4 * 4 + 0] += p1 * v.x; acc1[i4 * 4 + 1] += p1 * v.y;
                acc1[i4 * 4 + 2] += p1 * v.z; acc1[i4 * 4 + 3] += p1 * v.w;
            }
        }
        __syncthreads();
    }

    float inv0 = 1.f / l0, inv1 = 1.f / l1;
    float* o0 = g_att + (size_t)(b * SEQ + qrow0) * 2048 + h * 128 + c * 16;
    float* o1 = g_att + (size_t)(b * SEQ + qrow1) * 2048 + h * 128 + c * 16;
    #pragma unroll
    for (int i4 = 0; i4 < 4; i4++) {
        reinterpret_cast<float4*>(o0)[i4] = make_float4(
            acc0[i4*4]*inv0, acc0[i4*4+1]*inv0, acc0[i4*4+2]*inv0, acc0[i4*4+3]*inv0);
        reinterpret_cast<float4*>(o1)[i4] = make_float4(
            acc1[i4*4]*inv1, acc1[i4*4+1]*inv1, acc1[i4*4+2]*inv1, acc1[i4*4+3]*inv1);
    }
}

// ---------------- launch ----------------
extern "C" void kernel_launch(void* const* d_in, const int* in_sizes, int n_in,
                              void* d_out, int out_size)
{
    const float* x    = (const float*)d_in[0];
    const float* Wqa  = (const float*)d_in[1];
    const float* Wqb  = (const float*)d_in[2];
    const float* Wkva = (const float*)d_in[3];
    const float* Wkvb = (const float*)d_in[4];
    const float* Wout = (const float*)d_in[5];
    float* out = (float*)d_out;

    float *q1, *q, *ckv, *kv, *att;
    cudaGetSymbolAddress((void**)&q1,  g_q1);
    cudaGetSymbolAddress((void**)&q,   g_q);
    cudaGetSymbolAddress((void**)&ckv, g_ckv);
    cudaGetSymbolAddress((void**)&kv,  g_kv);
    cudaGetSymbolAddress((void**)&att, g_att);

    cudaFuncSetAttribute(gemm_hmma,
                         cudaFuncAttributeMaxDynamicSharedMemorySize, GEMM_SMEM);
    cudaFuncSetAttribute(attn_kernel,
                         cudaFuncAttributeMaxDynamicSharedMemorySize, SMEM_ATTN);

    dim3 t(256);
    // q1 = x @ Wqa              [4096,2048]x[2048,512]
    gemm_hmma<<<dim3(8, 32),  t, GEMM_SMEM>>>(x, 2048, Wqa, 512,  q1, 512,  32);
    // q = q1 @ Wqb              [4096,512]x[512,3072]
    gemm_hmma<<<dim3(48, 32), t, GEMM_SMEM>>>(q1, 512, Wqb, 3072, q,  3072, 8);
    // ckv = x @ Wkva            [4096,2048]x[2048,576]
    gemm_hmma<<<dim3(9, 32),  t, GEMM_SMEM>>>(x, 2048, Wkva, 576, ckv, 576, 32);
    // in-place RoPE on q_pe / k_pe
    rope_kernel<<<4096, 544>>>();
    // kv = ckv[:, :512] @ Wkvb  [4096,512]x[512,4096]
    gemm_hmma<<<dim3(64, 32), t, GEMM_SMEM>>>(ckv, 576, Wkvb, 4096, kv, 4096, 8);
    // attention
    attn_kernel<<<dim3(32, NHEADS, 2), 256, SMEM_ATTN>>>();
    // out = att @ Wout          [4096,2048]x[2048,2048]
    gemm_hmma<<<dim3(32, 32), t, GEMM_SMEM>>>(att, 2048, Wout, 2048, out, 2048, 32);
}

// round 4
// speedup vs baseline: 1.5695x; 1.5695x over previous
#include <cuda_runtime.h>
#include <cuda_bf16.h>
#include <math.h>
#include <stdint.h>

#define SEQ    2048
#define NROWS  4096
#define NHEADS 16

// ---------------- fp32 scratch ----------------
__device__ float g_q1 [NROWS * 512];
__device__ float g_q  [NROWS * 3072];
__device__ float g_ckv[NROWS * 576];
__device__ float g_kv [NROWS * 4096];
__device__ float g_att[NROWS * 2048];

// ---------------- bf16 hi/lo planes ----------------
__device__ __nv_bfloat16 g_xh[NROWS * 2048],  g_xl[NROWS * 2048];
__device__ __nv_bfloat16 g_q1h[NROWS * 512],  g_q1l[NROWS * 512];
__device__ __nv_bfloat16 g_ch [NROWS * 512],  g_cl [NROWS * 512];
__device__ __nv_bfloat16 g_ah [NROWS * 2048], g_al [NROWS * 2048];
__device__ __nv_bfloat16 g_Wqah[2048 * 512],  g_Wqal[2048 * 512];
__device__ __nv_bfloat16 g_Wqbh[512 * 3072],  g_Wqbl[512 * 3072];
__device__ __nv_bfloat16 g_Wkvah[2048 * 576], g_Wkval[2048 * 576];
__device__ __nv_bfloat16 g_Wkvbh[512 * 4096], g_Wkvbl[512 * 4096];
__device__ __nv_bfloat16 g_Wouth[2048 * 2048], g_Woutl[2048 * 2048];

// ================= helpers =================
__device__ __forceinline__ uint32_t smem_u32(const void* p) {
    uint32_t a;
    asm("{ .reg .u64 t; cvta.to.shared.u64 t, %1; cvt.u32.u64 %0, t; }" : "=r"(a) : "l"(p));
    return a;
}
__device__ __forceinline__ void ldsm4(uint32_t& r0, uint32_t& r1, uint32_t& r2, uint32_t& r3,
                                      uint32_t addr) {
    asm volatile("ldmatrix.sync.aligned.m8n8.x4.shared.b16 {%0,%1,%2,%3}, [%4];"
                 : "=r"(r0), "=r"(r1), "=r"(r2), "=r"(r3) : "r"(addr));
}
__device__ __forceinline__ void ldsm2t(uint32_t& r0, uint32_t& r1, uint32_t addr) {
    asm volatile("ldmatrix.sync.aligned.m8n8.x2.trans.shared.b16 {%0,%1}, [%2];"
                 : "=r"(r0), "=r"(r1) : "r"(addr));
}
__device__ __forceinline__ void mma16816(float* c, const uint32_t* a, const uint32_t* b) {
    asm volatile(
        "mma.sync.aligned.m16n8k16.row.col.f32.bf16.bf16.f32 "
        "{%0,%1,%2,%3}, {%4,%5,%6,%7}, {%8,%9}, {%0,%1,%2,%3};"
        : "+f"(c[0]), "+f"(c[1]), "+f"(c[2]), "+f"(c[3])
        : "r"(a[0]), "r"(a[1]), "r"(a[2]), "r"(a[3]), "r"(b[0]), "r"(b[1]));
}
__device__ __forceinline__ void cp16(uint32_t saddr, const void* g) {
    asm volatile("cp.async.ca.shared.global [%0], [%1], 16;" :: "r"(saddr), "l"(g));
}
#define CP_COMMIT() asm volatile("cp.async.commit_group;" ::: "memory")
#define CP_WAIT(n)  asm volatile("cp.async.wait_group %0;" :: "n"(n) : "memory")

__device__ __forceinline__ uint32_t pack_bf2(__nv_bfloat16 a, __nv_bfloat16 b) {
    __nv_bfloat162 t(a, b);
    return *reinterpret_cast<uint32_t*>(&t);
}
__device__ __forceinline__ void cvt_split4(float4 v, uint2& hi, uint2& lo) {
    __nv_bfloat16 h0 = __float2bfloat16(v.x), h1 = __float2bfloat16(v.y),
                  h2 = __float2bfloat16(v.z), h3 = __float2bfloat16(v.w);
    __nv_bfloat16 l0 = __float2bfloat16(v.x - __bfloat162float(h0)),
                  l1 = __float2bfloat16(v.y - __bfloat162float(h1)),
                  l2 = __float2bfloat16(v.z - __bfloat162float(h2)),
                  l3 = __float2bfloat16(v.w - __bfloat162float(h3));
    hi.x = pack_bf2(h0, h1); hi.y = pack_bf2(h2, h3);
    lo.x = pack_bf2(l0, l1); lo.y = pack_bf2(l2, l3);
}

// ---------------- split-conversion kernels ----------------
__global__ void conv_split(const float* __restrict__ in,
                           __nv_bfloat16* __restrict__ hi,
                           __nv_bfloat16* __restrict__ lo, int n4)
{
    int i = blockIdx.x * blockDim.x + threadIdx.x;
    if (i < n4) {
        float4 v = reinterpret_cast<const float4*>(in)[i];
        uint2 h, l; cvt_split4(v, h, l);
        reinterpret_cast<uint2*>(hi)[i] = h;
        reinterpret_cast<uint2*>(lo)[i] = l;
    }
}
// ckv compressed part: rows 4096, first 512 of 576 cols
__global__ void conv_split_ckv()
{
    int i = blockIdx.x * blockDim.x + threadIdx.x;   // over 4096*128 float4s
    int r = i >> 7, c4 = i & 127;
    float4 v = *reinterpret_cast<const float4*>(g_ckv + (size_t)r * 576 + c4 * 4);
    uint2 h, l; cvt_split4(v, h, l);
    reinterpret_cast<uint2*>(g_ch)[r * 128 + c4] = h;
    reinterpret_cast<uint2*>(g_cl)[r * 128 + c4] = l;
}

// ================= HMMA bf16-split GEMM (pre-split inputs, cp.async 2-stage) =========
// C[M,N] = (Ah+Al)[M,K] @ (Bh+Bl)[K,N] three-pass. CTA 128x64, K-chunk 32, 256 thr.
#define KCH 32
#define ALD 40
#define BLD 72
#define A_PLANE (128 * ALD)                 // 5120 elems
#define B_PLANE (KCH * BLD)                 // 2304 elems
#define OFF_AH 0
#define OFF_AL A_PLANE
#define OFF_BH (2 * A_PLANE)
#define OFF_BL (2 * A_PLANE + B_PLANE)
#define STAGE_E (2 * A_PLANE + 2 * B_PLANE) // 14848 elems
#define GEMM_SMEM (2 * STAGE_E * 2)         // 59392 bytes

__global__ __launch_bounds__(256) void gemm_hmma(
    const __nv_bfloat16* __restrict__ Ah, const __nv_bfloat16* __restrict__ Al, int lda,
    const __nv_bfloat16* __restrict__ Bh, const __nv_bfloat16* __restrict__ Bl, int ldb,
    float* __restrict__ C, int ldc, int nchunks)
{
    extern __shared__ __nv_bfloat16 sm[];
    const int tid  = threadIdx.x;
    const int wid  = tid >> 5;
    const int lane = tid & 31;
    const int m0 = blockIdx.y * 128;
    const int n0 = blockIdx.x * 64;
    const int mw = (wid & 3) * 32;
    const int nw = (wid >> 2) * 32;
    const uint32_t sm_base = smem_u32(sm);

    float acc[2][4][4];
    #pragma unroll
    for (int i = 0; i < 2; i++)
        #pragma unroll
        for (int j = 0; j < 4; j++)
            #pragma unroll
            for (int e = 0; e < 4; e++) acc[i][j][e] = 0.f;

    // per-thread cp.async source/dest fragments
    const int ar  = tid >> 1;                 // A: rows, 2 segs per thread
    const int as  = (tid & 1) * 2;            //   segs {0,1} or {2,3}
    const int br  = tid >> 3;                 // B: 32 rows x 8 segs
    const int bs  = tid & 7;

    const uint32_t aRow = lane & 15;
    const uint32_t aCol = (lane >> 4) * 8;
    const uint32_t aHoff = (uint32_t)(OFF_AH + (mw + aRow) * ALD + aCol) * 2;
    const uint32_t aLoff = (uint32_t)(OFF_AL + (mw + aRow) * ALD + aCol) * 2;
    const uint32_t bHoff = (uint32_t)(OFF_BH + (lane & 15) * BLD + nw) * 2;
    const uint32_t bLoff = (uint32_t)(OFF_BL + (lane & 15) * BLD + nw) * 2;

    auto load_stage = [&](int stg, int ch) {
        const uint32_t sb = sm_base + (uint32_t)stg * (STAGE_E * 2);
        const int k0 = ch * KCH;
        #pragma unroll
        for (int s = 0; s < 2; s++) {
            int seg = as + s;
            cp16(sb + (uint32_t)(OFF_AH + ar * ALD + seg * 8) * 2,
                 Ah + (size_t)(m0 + ar) * lda + k0 + seg * 8);
            cp16(sb + (uint32_t)(OFF_AL + ar * ALD + seg * 8) * 2,
                 Al + (size_t)(m0 + ar) * lda + k0 + seg * 8);
        }
        cp16(sb + (uint32_t)(OFF_BH + br * BLD + bs * 8) * 2,
             Bh + (size_t)(k0 + br) * ldb + n0 + bs * 8);
        cp16(sb + (uint32_t)(OFF_BL + br * BLD + bs * 8) * 2,
             Bl + (size_t)(k0 + br) * ldb + n0 + bs * 8);
    };

    load_stage(0, 0);
    CP_COMMIT();

    for (int ch = 0; ch < nchunks; ch++) {
        const int stg = ch & 1;
        if (ch + 1 < nchunks) {
            load_stage(stg ^ 1, ch + 1);
            CP_COMMIT();
            CP_WAIT(1);
        } else {
            CP_WAIT(0);
        }
        __syncthreads();

        const uint32_t sb = sm_base + (uint32_t)stg * (STAGE_E * 2);
        #pragma unroll
        for (int ks = 0; ks < 2; ks++) {
            const uint32_t kA = (uint32_t)(ks * 16) * 2;
            const uint32_t kB = (uint32_t)(ks * 16 * BLD) * 2;
            uint32_t aH[2][4], aL[2][4], bH[4][2], bL[4][2];
            #pragma unroll
            for (int mi = 0; mi < 2; mi++) {
                uint32_t off = (uint32_t)(mi * 16 * ALD) * 2 + kA;
                ldsm4(aH[mi][0], aH[mi][1], aH[mi][2], aH[mi][3], sb + aHoff + off);
                ldsm4(aL[mi][0], aL[mi][1], aL[mi][2], aL[mi][3], sb + aLoff + off);
            }
            #pragma unroll
            for (int ni = 0; ni < 4; ni++) {
                uint32_t off = kB + (uint32_t)(ni * 8) * 2;
                ldsm2t(bH[ni][0], bH[ni][1], sb + bHoff + off);
                ldsm2t(bL[ni][0], bL[ni][1], sb + bLoff + off);
            }
            #pragma unroll
            for (int mi = 0; mi < 2; mi++)
                #pragma unroll
                for (int ni = 0; ni < 4; ni++) {
                    mma16816(acc[mi][ni], aH[mi], bH[ni]);
                    mma16816(acc[mi][ni], aH[mi], bL[ni]);
                    mma16816(acc[mi][ni], aL[mi], bH[ni]);
                }
        }
        __syncthreads();
    }

    const int cr = lane >> 2;
    const int cc = (lane & 3) * 2;
    #pragma unroll
    for (int mi = 0; mi < 2; mi++)
        #pragma unroll
        for (int ni = 0; ni < 4; ni++) {
            int row = m0 + mw + mi * 16 + cr;
            int col = n0 + nw + ni * 8 + cc;
            *reinterpret_cast<float2*>(C + (size_t)row * ldc + col) =
                make_float2(acc[mi][ni][0], acc[mi][ni][1]);
            *reinterpret_cast<float2*>(C + (size_t)(row + 8) * ldc + col) =
                make_float2(acc[mi][ni][2], acc[mi][ni][3]);
        }
}

// ---------------- RoPE (fp32) ----------------
__global__ void rope_kernel()
{
    const int row  = blockIdx.x;
    const int pos  = row & (SEQ - 1);
    const int warp = threadIdx.x >> 5;
    const int lane = threadIdx.x & 31;

    float theta = __powf(10000.0f, -(float)lane * (1.0f / 32.0f));
    float ang = (float)pos * theta;
    float s, c;
    sincosf(ang, &s, &c);

    float* p;
    if (warp < 16)
        p = g_q + (size_t)row * 3072 + warp * 192 + 128 + 2 * lane;
    else
        p = g_ckv + (size_t)row * 576 + 512 + 2 * lane;

    float x1 = p[0], x2 = p[1];
    p[0] = x1 * c - x2 * s;
    p[1] = x1 * s + x2 * c;
}

// ---------------- flash attention (fp32 SIMT) ----------------
#define QS_LD 196
#define KS_LD 196
#define VS_LD 132
#define PS_LD 33
#define SMEM_ATTN ((64 * QS_LD + 32 * KS_LD + 32 * VS_LD + 64 * PS_LD) * 4)

__global__ __launch_bounds__(256, 1) void attn_kernel()
{
    extern __shared__ float smf[];
    float* Qs = smf;
    float* Ks = Qs + 64 * QS_LD;
    float* Vs = Ks + 32 * KS_LD;
    float* Ps = Vs + 32 * VS_LD;

    const int b = blockIdx.z, h = blockIdx.y;
    const int q0 = blockIdx.x * 64;
    const int tid = threadIdx.x;
    const int g = tid >> 3;
    const int c = tid & 7;
    const float scale = 0.07216878364870323f;

    for (int i = tid; i < 64 * 48; i += 256) {
        int r = i / 48, d4 = i - r * 48;
        float4 v = reinterpret_cast<const float4*>(
            g_q + (size_t)(b * SEQ + q0 + r) * 3072 + h * 192)[d4];
        reinterpret_cast<float4*>(Qs + r * QS_LD)[d4] = v;
    }

    const int qrow0 = q0 + 2 * g;
    const int qrow1 = qrow0 + 1;

    float m0 = -INFINITY, m1 = -INFINITY, l0 = 0.f, l1 = 0.f;
    float acc0[16], acc1[16];
    #pragma unroll
    for (int i = 0; i < 16; i++) { acc0[i] = 0.f; acc1[i] = 0.f; }

    for (int k0 = 0; k0 < q0 + 64; k0 += 32) {
        for (int i = tid; i < 32 * 32; i += 256) {
            int r = i >> 5, d4 = i & 31;
            reinterpret_cast<float4*>(Ks + r * KS_LD)[d4] =
                reinterpret_cast<const float4*>(
                    g_kv + (size_t)(b * SEQ + k0 + r) * 4096 + h * 256)[d4];
        }
        for (int i = tid; i < 32 * 16; i += 256) {
            int r = i >> 4, d4 = i & 15;
            reinterpret_cast<float4*>(Ks + r * KS_LD + 128)[d4] =
                reinterpret_cast<const float4*>(
                    g_ckv + (size_t)(b * SEQ + k0 + r) * 576 + 512)[d4];
        }
        for (int i = tid; i < 32 * 32; i += 256) {
            int r = i >> 5, d4 = i & 31;
            reinterpret_cast<float4*>(Vs + r * VS_LD)[d4] =
                reinterpret_cast<const float4*>(
                    g_kv + (size_t)(b * SEQ + k0 + r) * 4096 + h * 256 + 128)[d4];
        }
        __syncthreads();

        float sA[4] = {0, 0, 0, 0}, sB[4] = {0, 0, 0, 0};
        const float4* qp0 = reinterpret_cast<const float4*>(Qs + (2 * g)     * QS_LD);
        const float4* qp1 = reinterpret_cast<const float4*>(Qs + (2 * g + 1) * QS_LD);
        const float4* kp0 = reinterpret_cast<const float4*>(Ks + (c * 4 + 0) * KS_LD);
        const float4* kp1 = reinterpret_cast<const float4*>(Ks + (c * 4 + 1) * KS_LD);
        const float4* kp2 = reinterpret_cast<const float4*>(Ks + (c * 4 + 2) * KS_LD);
        const float4* kp3 = reinterpret_cast<const float4*>(Ks + (c * 4 + 3) * KS_LD);
        #pragma unroll 8
        for (int d4 = 0; d4 < 48; d4++) {
            float4 qa = qp0[d4], qb = qp1[d4];
            float4 k;
            k = kp0[d4];
            sA[0] += qa.x*k.x + qa.y*k.y + qa.z*k.z + qa.w*k.w;
            sB[0] += qb.x*k.x + qb.y*k.y + qb.z*k.z + qb.w*k.w;
            k = kp1[d4];
            sA[1] += qa.x*k.x + qa.y*k.y + qa.z*k.z + qa.w*k.w;
            sB[1] += qb.x*k.x + qb.y*k.y + qb.z*k.z + qb.w*k.w;
            k = kp2[d4];
            sA[2] += qa.x*k.x + qa.y*k.y + qa.z*k.z + qa.w*k.w;
            sB[2] += qb.x*k.x + qb.y*k.y + qb.z*k.z + qb.w*k.w;
            k = kp3[d4];
            sA[3] += qa.x*k.x + qa.y*k.y + qa.z*k.z + qa.w*k.w;
            sB[3] += qb.x*k.x + qb.y*k.y + qb.z*k.z + qb.w*k.w;
        }

        #pragma unroll
        for (int j = 0; j < 4; j++) {
            int kidx = k0 + c * 4 + j;
            sA[j] = (kidx <= qrow0) ? sA[j] * scale : -INFINITY;
            sB[j] = (kidx <= qrow1) ? sB[j] * scale : -INFINITY;
        }

        float t0 = fmaxf(fmaxf(sA[0], sA[1]), fmaxf(sA[2], sA[3]));
        float t1 = fmaxf(fmaxf(sB[0], sB[1]), fmaxf(sB[2], sB[3]));
        #pragma unroll
        for (int off = 1; off < 8; off <<= 1) {
            t0 = fmaxf(t0, __shfl_xor_sync(0xffffffffu, t0, off));
            t1 = fmaxf(t1, __shfl_xor_sync(0xffffffffu, t1, off));
        }
        float mn0 = fmaxf(m0, t0), mn1 = fmaxf(m1, t1);
        float a0 = expf(m0 - mn0), a1 = expf(m1 - mn1);
        m0 = mn0; m1 = mn1;

        float pA[4], pB[4];
        float ps0 = 0.f, ps1 = 0.f;
        #pragma unroll
        for (int j = 0; j < 4; j++) {
            pA[j] = expf(sA[j] - m0); ps0 += pA[j];
            pB[j] = expf(sB[j] - m1); ps1 += pB[j];
        }
        #pragma unroll
        for (int off = 1; off < 8; off <<= 1) {
            ps0 += __shfl_xor_sync(0xffffffffu, ps0, off);
            ps1 += __shfl_xor_sync(0xffffffffu, ps1, off);
        }
        l0 = l0 * a0 + ps0;
        l1 = l1 * a1 + ps1;

        #pragma unroll
        for (int j = 0; j < 4; j++) {
            Ps[(2 * g)     * PS_LD + c * 4 + j] = pA[j];
            Ps[(2 * g + 1) * PS_LD + c * 4 + j] = pB[j];
        }
        #pragma unroll
        for (int i = 0; i < 16; i++) { acc0[i] *= a0; acc1[i] *= a1; }
        __syncthreads();

        const float* pr0 = Ps + (2 * g)     * PS_LD;
        const float* pr1 = Ps + (2 * g + 1) * PS_LD;
        #pragma unroll 4
        for (int j = 0; j < 32; j++) {
            float p0 = pr0[j], p1 = pr1[j];
            const float4* vr = reinterpret_cast<const float4*>(Vs + j * VS_LD + c * 16);
            #pragma unroll
            for (int i4 = 0; i4 < 4; i4++) {
                float4 v = vr[i4];
                acc0[i4 * 4 + 0] += p0 * v.x; acc0[i4 * 4 + 1] += p0 * v.y;
                acc0[i4 * 4 + 2] += p0 * v.z; acc0[i4 * 4 + 3] += p0 * v.w;
                acc1[i4 * 4 + 0] += p1 * v.x; acc1[i4 * 4 + 1] += p1 * v.y;
                acc1[i4 * 4 + 2] += p1 * v.z; acc1[i4 * 4 + 3] += p1 * v.w;
            }
        }
        __syncthreads();
    }

    float inv0 = 1.f / l0, inv1 = 1.f / l1;
    float* o0 = g_att + (size_t)(b * SEQ + qrow0) * 2048 + h * 128 + c * 16;
    float* o1 = g_att + (size_t)(b * SEQ + qrow1) * 2048 + h * 128 + c * 16;
    #pragma unroll
    for (int i4 = 0; i4 < 4; i4++) {
        reinterpret_cast<float4*>(o0)[i4] = make_float4(
            acc0[i4*4]*inv0, acc0[i4*4+1]*inv0, acc0[i4*4+2]*inv0, acc0[i4*4+3]*inv0);
        reinterpret_cast<float4*>(o1)[i4] = make_float4(
            acc1[i4*4]*inv1, acc1[i4*4+1]*inv1, acc1[i4*4+2]*inv1, acc1[i4*4+3]*inv1);
    }
}

// ---------------- launch ----------------
static inline void conv(const float* in, __nv_bfloat16* hi, __nv_bfloat16* lo, int nelem)
{
    int n4 = nelem / 4;
    conv_split<<<(n4 + 255) / 256, 256>>>(in, hi, lo, n4);
}

extern "C" void kernel_launch(void* const* d_in, const int* in_sizes, int n_in,
                              void* d_out, int out_size)
{
    const float* x    = (const float*)d_in[0];
    const float* Wqa  = (const float*)d_in[1];
    const float* Wqb  = (const float*)d_in[2];
    const float* Wkva = (const float*)d_in[3];
    const float* Wkvb = (const float*)d_in[4];
    const float* Wout = (const float*)d_in[5];
    float* out = (float*)d_out;

    float *q1, *q, *ckv, *kv, *att;
    cudaGetSymbolAddress((void**)&q1,  g_q1);
    cudaGetSymbolAddress((void**)&q,   g_q);
    cudaGetSymbolAddress((void**)&ckv, g_ckv);
    cudaGetSymbolAddress((void**)&kv,  g_kv);
    cudaGetSymbolAddress((void**)&att, g_att);

    __nv_bfloat16 *xh, *xl, *q1h, *q1l, *ch, *cl, *ah, *al;
    __nv_bfloat16 *wqah, *wqal, *wqbh, *wqbl, *wkvah, *wkval, *wkvbh, *wkvbl, *wouth, *woutl;
    cudaGetSymbolAddress((void**)&xh,   g_xh);   cudaGetSymbolAddress((void**)&xl,   g_xl);
    cudaGetSymbolAddress((void**)&q1h,  g_q1h);  cudaGetSymbolAddress((void**)&q1l,  g_q1l);
    cudaGetSymbolAddress((void**)&ch,   g_ch);   cudaGetSymbolAddress((void**)&cl,   g_cl);
    cudaGetSymbolAddress((void**)&ah,   g_ah);   cudaGetSymbolAddress((void**)&al,   g_al);
    cudaGetSymbolAddress((void**)&wqah, g_Wqah); cudaGetSymbolAddress((void**)&wqal, g_Wqal);
    cudaGetSymbolAddress((void**)&wqbh, g_Wqbh); cudaGetSymbolAddress((void**)&wqbl, g_Wqbl);
    cudaGetSymbolAddress((void**)&wkvah, g_Wkvah); cudaGetSymbolAddress((void**)&wkval, g_Wkval);
    cudaGetSymbolAddress((void**)&wkvbh, g_Wkvbh); cudaGetSymbolAddress((void**)&wkvbl, g_Wkvbl);
    cudaGetSymbolAddress((void**)&wouth, g_Wouth); cudaGetSymbolAddress((void**)&woutl, g_Woutl);

    cudaFuncSetAttribute(gemm_hmma,
                         cudaFuncAttributeMaxDynamicSharedMemorySize, GEMM_SMEM);
    cudaFuncSetAttribute(attn_kernel,
                         cudaFuncAttributeMaxDynamicSharedMemorySize, SMEM_ATTN);

    // ---- pre-split conversions (weights + x) ----
    conv(x,    xh,    xl,    NROWS * 2048);
    conv(Wqa,  wqah,  wqal,  2048 * 512);
    conv(Wqb,  wqbh,  wqbl,  512 * 3072);
    conv(Wkva, wkvah, wkval, 2048 * 576);
    conv(Wkvb, wkvbh, wkvbl, 512 * 4096);
    conv(Wout, wouth, woutl, 2048 * 2048);

    dim3 t(256);
    // q1 = x @ Wqa                 [4096,2048]x[2048,512]
    gemm_hmma<<<dim3(8, 32),  t, GEMM_SMEM>>>(xh, xl, 2048, wqah, wqal, 512,  q1, 512,  64);
    conv(q1, q1h, q1l, NROWS * 512);
    // q = q1 @ Wqb                 [4096,512]x[512,3072]
    gemm_hmma<<<dim3(48, 32), t, GEMM_SMEM>>>(q1h, q1l, 512, wqbh, wqbl, 3072, q, 3072, 16);
    // ckv = x @ Wkva               [4096,2048]x[2048,576]
    gemm_hmma<<<dim3(9, 32),  t, GEMM_SMEM>>>(xh, xl, 2048, wkvah, wkval, 576, ckv, 576, 64);
    // rope on q_pe / k_pe (fp32, before compressing conv which reads cols 0..511 only)
    rope_kernel<<<4096, 544>>>();
    // split compressed ckv
    conv_split_ckv<<<(NROWS * 128 + 255) / 256, 256>>>();
    // kv = ckv_c @ Wkvb            [4096,512]x[512,4096]
    gemm_hmma<<<dim3(64, 32), t, GEMM_SMEM>>>(ch, cl, 512, wkvbh, wkvbl, 4096, kv, 4096, 16);
    // attention
    attn_kernel<<<dim3(32, NHEADS, 2), 256, SMEM_ATTN>>>();
    conv(att, ah, al, NROWS * 2048);
    // out = att @ Wout             [4096,2048]x[2048,2048]
    gemm_hmma<<<dim3(32, 32), t, GEMM_SMEM>>>(ah, al, 2048, wouth, woutl, 2048, out, 2048, 64);
}

// round 9
// speedup vs baseline: 6.4201x; 4.0905x over previous
#include <cuda_runtime.h>
#include <cuda_bf16.h>
#include <math.h>
#include <stdint.h>

#define SEQ    2048
#define NROWS  4096
#define NHEADS 16

// ---------------- fp32 scratch ----------------
__device__ float g_q1 [NROWS * 512];
__device__ float g_q  [NROWS * 3072];
__device__ float g_ckv[NROWS * 576];
__device__ float g_kv [NROWS * 4096];
__device__ float g_att[NROWS * 2048];

// ---------------- bf16 hi/lo planes (GEMMs) ----------------
__device__ __nv_bfloat16 g_xh[NROWS * 2048],  g_xl[NROWS * 2048];
__device__ __nv_bfloat16 g_q1h[NROWS * 512],  g_q1l[NROWS * 512];
__device__ __nv_bfloat16 g_ch [NROWS * 512],  g_cl [NROWS * 512];
__device__ __nv_bfloat16 g_ah [NROWS * 2048], g_al [NROWS * 2048];
__device__ __nv_bfloat16 g_Wqah[2048 * 512],  g_Wqal[2048 * 512];
__device__ __nv_bfloat16 g_Wqbh[512 * 3072],  g_Wqbl[512 * 3072];
__device__ __nv_bfloat16 g_Wkvah[2048 * 576], g_Wkval[2048 * 576];
__device__ __nv_bfloat16 g_Wkvbh[512 * 4096], g_Wkvbl[512 * 4096];
__device__ __nv_bfloat16 g_Wouth[2048 * 2048], g_Woutl[2048 * 2048];

// ---------------- bf16 hi/lo planes (attention) ----------------
__device__ __nv_bfloat16 g_qbh[NROWS * 3072], g_qbl[NROWS * 3072];
__device__ __nv_bfloat16 g_kvh[NROWS * 4096], g_kvl[NROWS * 4096];
__device__ __nv_bfloat16 g_peh[NROWS * 64],   g_pel[NROWS * 64];

// ================= helpers =================
__device__ __forceinline__ uint32_t smem_u32(const void* p) {
    uint32_t a;
    asm("{ .reg .u64 t; cvta.to.shared.u64 t, %1; cvt.u32.u64 %0, t; }" : "=r"(a) : "l"(p));
    return a;
}
__device__ __forceinline__ void ldsm4(uint32_t& r0, uint32_t& r1, uint32_t& r2, uint32_t& r3,
                                      uint32_t addr) {
    asm volatile("ldmatrix.sync.aligned.m8n8.x4.shared.b16 {%0,%1,%2,%3}, [%4];"
                 : "=r"(r0), "=r"(r1), "=r"(r2), "=r"(r3) : "r"(addr));
}
__device__ __forceinline__ void ldsm2t(uint32_t& r0, uint32_t& r1, uint32_t addr) {
    asm volatile("ldmatrix.sync.aligned.m8n8.x2.trans.shared.b16 {%0,%1}, [%2];"
                 : "=r"(r0), "=r"(r1) : "r"(addr));
}
__device__ __forceinline__ void mma16816(float* c, const uint32_t* a, const uint32_t* b) {
    asm volatile(
        "mma.sync.aligned.m16n8k16.row.col.f32.bf16.bf16.f32 "
        "{%0,%1,%2,%3}, {%4,%5,%6,%7}, {%8,%9}, {%0,%1,%2,%3};"
        : "+f"(c[0]), "+f"(c[1]), "+f"(c[2]), "+f"(c[3])
        : "r"(a[0]), "r"(a[1]), "r"(a[2]), "r"(a[3]), "r"(b[0]), "r"(b[1]));
}
__device__ __forceinline__ void cp16(uint32_t saddr, const void* g) {
    asm volatile("cp.async.ca.shared.global [%0], [%1], 16;" :: "r"(saddr), "l"(g));
}
#define CP_COMMIT() asm volatile("cp.async.commit_group;" ::: "memory")
#define CP_WAIT(n)  asm volatile("cp.async.wait_group %0;" :: "n"(n) : "memory")

__device__ __forceinline__ uint32_t pack_bf2(__nv_bfloat16 a, __nv_bfloat16 b) {
    __nv_bfloat162 t(a, b);
    return *reinterpret_cast<uint32_t*>(&t);
}
__device__ __forceinline__ void cvt_split4(float4 v, uint2& hi, uint2& lo) {
    __nv_bfloat16 h0 = __float2bfloat16(v.x), h1 = __float2bfloat16(v.y),
                  h2 = __float2bfloat16(v.z), h3 = __float2bfloat16(v.w);
    __nv_bfloat16 l0 = __float2bfloat16(v.x - __bfloat162float(h0)),
                  l1 = __float2bfloat16(v.y - __bfloat162float(h1)),
                  l2 = __float2bfloat16(v.z - __bfloat162float(h2)),
                  l3 = __float2bfloat16(v.w - __bfloat162float(h3));
    hi.x = pack_bf2(h0, h1); hi.y = pack_bf2(h2, h3);
    lo.x = pack_bf2(l0, l1); lo.y = pack_bf2(l2, l3);
}

// ---------------- conversion kernels ----------------
__global__ void conv_split(const float* __restrict__ in,
                           __nv_bfloat16* __restrict__ hi,
                           __nv_bfloat16* __restrict__ lo, int n4)
{
    int i = blockIdx.x * blockDim.x + threadIdx.x;
    if (i < n4) {
        float4 v = reinterpret_cast<const float4*>(in)[i];
        uint2 h, l; cvt_split4(v, h, l);
        reinterpret_cast<uint2*>(hi)[i] = h;
        reinterpret_cast<uint2*>(lo)[i] = l;
    }
}
__global__ void conv_split_ckv()
{
    int i = blockIdx.x * blockDim.x + threadIdx.x;
    int r = i >> 7, c4 = i & 127;
    float4 v = *reinterpret_cast<const float4*>(g_ckv + (size_t)r * 576 + c4 * 4);
    uint2 h, l; cvt_split4(v, h, l);
    reinterpret_cast<uint2*>(g_ch)[r * 128 + c4] = h;
    reinterpret_cast<uint2*>(g_cl)[r * 128 + c4] = l;
}
__global__ void conv_split_pe()
{
    int i = blockIdx.x * blockDim.x + threadIdx.x;   // over 4096*16 float4
    int r = i >> 4, c4 = i & 15;
    float4 v = *reinterpret_cast<const float4*>(g_ckv + (size_t)r * 576 + 512 + c4 * 4);
    uint2 h, l; cvt_split4(v, h, l);
    reinterpret_cast<uint2*>(g_peh)[r * 16 + c4] = h;
    reinterpret_cast<uint2*>(g_pel)[r * 16 + c4] = l;
}

// ================= HMMA bf16-split GEMM (validated R4) =========
#define KCH 32
#define ALD 40
#define BLD 72
#define A_PLANE (128 * ALD)
#define B_PLANE (KCH * BLD)
#define OFF_AH 0
#define OFF_AL A_PLANE
#define OFF_BH (2 * A_PLANE)
#define OFF_BL (2 * A_PLANE + B_PLANE)
#define STAGE_E (2 * A_PLANE + 2 * B_PLANE)
#define GEMM_SMEM (2 * STAGE_E * 2)

__global__ __launch_bounds__(256) void gemm_hmma(
    const __nv_bfloat16* __restrict__ Ah, const __nv_bfloat16* __restrict__ Al, int lda,
    const __nv_bfloat16* __restrict__ Bh, const __nv_bfloat16* __restrict__ Bl, int ldb,
    float* __restrict__ C, int ldc, int nchunks)
{
    extern __shared__ __nv_bfloat16 sm[];
    const int tid  = threadIdx.x;
    const int wid  = tid >> 5;
    const int lane = tid & 31;
    const int m0 = blockIdx.y * 128;
    const int n0 = blockIdx.x * 64;
    const int mw = (wid & 3) * 32;
    const int nw = (wid >> 2) * 32;
    const uint32_t sm_base = smem_u32(sm);

    float acc[2][4][4];
    #pragma unroll
    for (int i = 0; i < 2; i++)
        #pragma unroll
        for (int j = 0; j < 4; j++)
            #pragma unroll
            for (int e = 0; e < 4; e++) acc[i][j][e] = 0.f;

    const int ar  = tid >> 1;
    const int as  = (tid & 1) * 2;
    const int br  = tid >> 3;
    const int bs  = tid & 7;

    const uint32_t aRow = lane & 15;
    const uint32_t aCol = (lane >> 4) * 8;
    const uint32_t aHoff = (uint32_t)(OFF_AH + (mw + aRow) * ALD + aCol) * 2;
    const uint32_t aLoff = (uint32_t)(OFF_AL + (mw + aRow) * ALD + aCol) * 2;
    const uint32_t bHoff = (uint32_t)(OFF_BH + (lane & 15) * BLD + nw) * 2;
    const uint32_t bLoff = (uint32_t)(OFF_BL + (lane & 15) * BLD + nw) * 2;

    auto load_stage = [&](int stg, int ch) {
        const uint32_t sb = sm_base + (uint32_t)stg * (STAGE_E * 2);
        const int k0 = ch * KCH;
        #pragma unroll
        for (int s = 0; s < 2; s++) {
            int seg = as + s;
            cp16(sb + (uint32_t)(OFF_AH + ar * ALD + seg * 8) * 2,
                 Ah + (size_t)(m0 + ar) * lda + k0 + seg * 8);
            cp16(sb + (uint32_t)(OFF_AL + ar * ALD + seg * 8) * 2,
                 Al + (size_t)(m0 + ar) * lda + k0 + seg * 8);
        }
        cp16(sb + (uint32_t)(OFF_BH + br * BLD + bs * 8) * 2,
             Bh + (size_t)(k0 + br) * ldb + n0 + bs * 8);
        cp16(sb + (uint32_t)(OFF_BL + br * BLD + bs * 8) * 2,
             Bl + (size_t)(k0 + br) * ldb + n0 + bs * 8);
    };

    load_stage(0, 0);
    CP_COMMIT();

    for (int ch = 0; ch < nchunks; ch++) {
        const int stg = ch & 1;
        if (ch + 1 < nchunks) {
            load_stage(stg ^ 1, ch + 1);
            CP_COMMIT();
            CP_WAIT(1);
        } else {
            CP_WAIT(0);
        }
        __syncthreads();

        const uint32_t sb = sm_base + (uint32_t)stg * (STAGE_E * 2);
        #pragma unroll
        for (int ks = 0; ks < 2; ks++) {
            const uint32_t kA = (uint32_t)(ks * 16) * 2;
            const uint32_t kB = (uint32_t)(ks * 16 * BLD) * 2;
            uint32_t aH[2][4], aL[2][4], bH[4][2], bL[4][2];
            #pragma unroll
            for (int mi = 0; mi < 2; mi++) {
                uint32_t off = (uint32_t)(mi * 16 * ALD) * 2 + kA;
                ldsm4(aH[mi][0], aH[mi][1], aH[mi][2], aH[mi][3], sb + aHoff + off);
                ldsm4(aL[mi][0], aL[mi][1], aL[mi][2], aL[mi][3], sb + aLoff + off);
            }
            #pragma unroll
            for (int ni = 0; ni < 4; ni++) {
                uint32_t off = kB + (uint32_t)(ni * 8) * 2;
                ldsm2t(bH[ni][0], bH[ni][1], sb + bHoff + off);
                ldsm2t(bL[ni][0], bL[ni][1], sb + bLoff + off);
            }
            #pragma unroll
            for (int mi = 0; mi < 2; mi++)
                #pragma unroll
                for (int ni = 0; ni < 4; ni++) {
                    mma16816(acc[mi][ni], aH[mi], bH[ni]);
                    mma16816(acc[mi][ni], aH[mi], bL[ni]);
                    mma16816(acc[mi][ni], aL[mi], bH[ni]);
                }
        }
        __syncthreads();
    }

    const int cr = lane >> 2;
    const int cc = (lane & 3) * 2;
    #pragma unroll
    for (int mi = 0; mi < 2; mi++)
        #pragma unroll
        for (int ni = 0; ni < 4; ni++) {
            int row = m0 + mw + mi * 16 + cr;
            int col = n0 + nw + ni * 8 + cc;
            *reinterpret_cast<float2*>(C + (size_t)row * ldc + col) =
                make_float2(acc[mi][ni][0], acc[mi][ni][1]);
            *reinterpret_cast<float2*>(C + (size_t)(row + 8) * ldc + col) =
                make_float2(acc[mi][ni][2], acc[mi][ni][3]);
        }
}

// ---------------- RoPE (fp32) ----------------
__global__ void rope_kernel()
{
    const int row  = blockIdx.x;
    const int pos  = row & (SEQ - 1);
    const int warp = threadIdx.x >> 5;
    const int lane = threadIdx.x & 31;

    float theta = __powf(10000.0f, -(float)lane * (1.0f / 32.0f));
    float ang = (float)pos * theta;
    float s, c;
    sincosf(ang, &s, &c);

    float* p;
    if (warp < 16)
        p = g_q + (size_t)row * 3072 + warp * 192 + 128 + 2 * lane;
    else
        p = g_ckv + (size_t)row * 576 + 512 + 2 * lane;

    float x1 = p[0], x2 = p[1];
    p[0] = x1 * c - x2 * s;
    p[1] = x1 * s + x2 * c;
}

// ================= HMMA flash attention, bf16 3-pass split =================
// Block 256 thr (8 warps, 16 q-rows each), q-tile 128, key tiles of 32 double-buffered.
#define QT 128
#define KT 32
#define QLD 200
#define KLD 200
#define VLD 136
#define AQ_H 0
#define AQ_L (QT * QLD)                       // 25600
#define AK   (2 * QT * QLD)                   // 51200
#define K_STG (2 * KT * KLD)                  // 12800 (2 planes)
#define K_PL  (KT * KLD)                      // 6400
#define AV   (AK + 2 * K_STG)                 // 76800
#define V_STG (2 * KT * VLD)                  // 8704
#define V_PL  (KT * VLD)                      // 4352
#define ATT_E (AV + 2 * V_STG)                // 94208 elems
#define ATT_SMEM (ATT_E * 2)                  // 188416 bytes

__global__ __launch_bounds__(256, 1) void attn_hmma()
{
    extern __shared__ __nv_bfloat16 sm[];
    const int tid = threadIdx.x, wid = tid >> 5, lane = tid & 31;
    const int b = blockIdx.z, h = blockIdx.y;
    const int q0 = blockIdx.x * QT;
    const uint32_t sb = smem_u32(sm);
    const float scale = 0.07216878364870323f;   // 1/sqrt(192)

    // ---- async load Q tile hi/lo ([128][192] each) ----
    {
        int r = tid >> 1;
        size_t row = (size_t)(b * SEQ + q0 + r) * 3072 + h * 192;
        const __nv_bfloat16* srch = g_qbh + row;
        const __nv_bfloat16* srcl = g_qbl + row;
        uint32_t dsth = sb + (uint32_t)(AQ_H + r * QLD) * 2;
        uint32_t dstl = sb + (uint32_t)(AQ_L + r * QLD) * 2;
        #pragma unroll
        for (int s = 0; s < 12; s++) {
            int seg = (tid & 1) * 12 + s;
            cp16(dsth + seg * 16, srch + seg * 8);
            cp16(dstl + seg * 16, srcl + seg * 8);
        }
    }

    // ---- K/V stage loader: K = [nope(16 segs)|pe(8 segs)] hi/lo, V hi/lo ----
    auto load_kv = [&](int stg, int kt0) {
        int r = tid >> 3;                     // 32 rows, 8 threads/row
        size_t row = (size_t)(b * SEQ + kt0 + r);
        const __nv_bfloat16* knh = g_kvh + row * 4096 + h * 256;
        const __nv_bfloat16* knl = g_kvl + row * 4096 + h * 256;
        const __nv_bfloat16* peh = g_peh + row * 64;
        const __nv_bfloat16* pel = g_pel + row * 64;
        uint32_t kdh = sb + (uint32_t)(AK + stg * K_STG + r * KLD) * 2;
        uint32_t kdl = kdh + (uint32_t)K_PL * 2;
        uint32_t vdh = sb + (uint32_t)(AV + stg * V_STG + r * VLD) * 2;
        uint32_t vdl = vdh + (uint32_t)V_PL * 2;
        #pragma unroll
        for (int s = 0; s < 10; s++) {
            int seg = (tid & 7) * 10 + s;
            if (seg < 16)      cp16(kdh + seg * 16, knh + seg * 8);
            else if (seg < 24) cp16(kdh + seg * 16, peh + (seg - 16) * 8);
            else if (seg < 40) cp16(kdl + (seg - 24) * 16, knl + (seg - 24) * 8);
            else if (seg < 48) cp16(kdl + (seg - 24) * 16, pel + (seg - 40) * 8);
            else if (seg < 64) cp16(vdh + (seg - 48) * 16, knh + 128 + (seg - 48) * 8);
            else               cp16(vdl + (seg - 64) * 16, knl + 128 + (seg - 64) * 8);
        }
    };

    load_kv(0, 0);
    CP_COMMIT();

    const int ntiles = q0 / KT + QT / KT;
    float m0 = -INFINITY, m1 = -INFINITY, l0 = 0.f, l1 = 0.f;
    float O[16][4];
    #pragma unroll
    for (int od = 0; od < 16; od++)
        #pragma unroll
        for (int e = 0; e < 4; e++) O[od][e] = 0.f;

    const uint32_t qb_h = sb + (uint32_t)(AQ_H + (wid * 16 + (lane & 15)) * QLD + (lane >> 4) * 8) * 2;
    const uint32_t qb_l = qb_h + (uint32_t)(QT * QLD) * 2;

    for (int t = 0; t < ntiles; t++) {
        const int stg = t & 1;
        if (t + 1 < ntiles) {
            load_kv(stg ^ 1, (t + 1) * KT);
            CP_COMMIT();
            CP_WAIT(1);
        } else {
            CP_WAIT(0);
        }
        __syncthreads();

        // ---- S = Q K^T, 3-pass split ----
        float S[4][4];
        #pragma unroll
        for (int g = 0; g < 4; g++)
            #pragma unroll
            for (int e = 0; e < 4; e++) S[g][e] = 0.f;

        const uint32_t kb_h = sb + (uint32_t)(AK + stg * K_STG + (lane & 15) * KLD + (lane >> 4) * 8) * 2;
        const uint32_t kb_l = kb_h + (uint32_t)K_PL * 2;
        #pragma unroll
        for (int ks = 0; ks < 12; ks++) {
            uint32_t aH[4], aL[4];
            ldsm4(aH[0], aH[1], aH[2], aH[3], qb_h + ks * 32);
            ldsm4(aL[0], aL[1], aL[2], aL[3], qb_l + ks * 32);
            #pragma unroll
            for (int np = 0; np < 2; np++) {
                uint32_t off = (uint32_t)(np * 16 * KLD) * 2 + ks * 32;
                uint32_t h0, h1, h2, h3, l0r, l1r, l2r, l3r;
                ldsm4(h0, h1, h2, h3, kb_h + off);
                ldsm4(l0r, l1r, l2r, l3r, kb_l + off);
                uint32_t bh0[2] = {h0, h2},  bh1[2] = {h1, h3};
                uint32_t bl0[2] = {l0r, l2r}, bl1[2] = {l1r, l3r};
                mma16816(S[np * 2],     aH, bh0);
                mma16816(S[np * 2],     aH, bl0);
                mma16816(S[np * 2],     aL, bh0);
                mma16816(S[np * 2 + 1], aH, bh1);
                mma16816(S[np * 2 + 1], aH, bl1);
                mma16816(S[np * 2 + 1], aL, bh1);
            }
        }

        // ---- scale + causal mask ----
        const int mrow0 = q0 + wid * 16 + (lane >> 2);
        const int kcol0 = t * KT + (lane & 3) * 2;
        const bool needmask = (t * KT + KT - 1) > (q0 + wid * 16);
        if (needmask) {
            #pragma unroll
            for (int g = 0; g < 4; g++) {
                int kc = kcol0 + g * 8;
                S[g][0] = (kc     <= mrow0)     ? S[g][0] * scale : -INFINITY;
                S[g][1] = (kc + 1 <= mrow0)     ? S[g][1] * scale : -INFINITY;
                S[g][2] = (kc     <= mrow0 + 8) ? S[g][2] * scale : -INFINITY;
                S[g][3] = (kc + 1 <= mrow0 + 8) ? S[g][3] * scale : -INFINITY;
            }
        } else {
            #pragma unroll
            for (int g = 0; g < 4; g++)
                #pragma unroll
                for (int e = 0; e < 4; e++) S[g][e] *= scale;
        }

        // ---- online softmax (fp32) ----
        float tm0 = -INFINITY, tm1 = -INFINITY;
        #pragma unroll
        for (int g = 0; g < 4; g++) {
            tm0 = fmaxf(tm0, fmaxf(S[g][0], S[g][1]));
            tm1 = fmaxf(tm1, fmaxf(S[g][2], S[g][3]));
        }
        tm0 = fmaxf(tm0, __shfl_xor_sync(0xffffffffu, tm0, 1));
        tm0 = fmaxf(tm0, __shfl_xor_sync(0xffffffffu, tm0, 2));
        tm1 = fmaxf(tm1, __shfl_xor_sync(0xffffffffu, tm1, 1));
        tm1 = fmaxf(tm1, __shfl_xor_sync(0xffffffffu, tm1, 2));

        float mn0 = fmaxf(m0, tm0), mn1 = fmaxf(m1, tm1);
        float al0 = __expf(m0 - mn0), al1 = __expf(m1 - mn1);
        m0 = mn0; m1 = mn1;

        float P[4][4];
        float s0 = 0.f, s1 = 0.f;
        #pragma unroll
        for (int g = 0; g < 4; g++) {
            P[g][0] = __expf(S[g][0] - m0); s0 += P[g][0];
            P[g][1] = __expf(S[g][1] - m0); s0 += P[g][1];
            P[g][2] = __expf(S[g][2] - m1); s1 += P[g][2];
            P[g][3] = __expf(S[g][3] - m1); s1 += P[g][3];
        }
        s0 += __shfl_xor_sync(0xffffffffu, s0, 1);
        s0 += __shfl_xor_sync(0xffffffffu, s0, 2);
        s1 += __shfl_xor_sync(0xffffffffu, s1, 1);
        s1 += __shfl_xor_sync(0xffffffffu, s1, 2);
        l0 = l0 * al0 + s0;
        l1 = l1 * al1 + s1;

        #pragma unroll
        for (int od = 0; od < 16; od++) {
            O[od][0] *= al0; O[od][1] *= al0;
            O[od][2] *= al1; O[od][3] *= al1;
        }

        // ---- P -> hi/lo bf16 a-frags ----
        uint32_t aPh[2][4], aPl[2][4];
        #pragma unroll
        for (int kp = 0; kp < 2; kp++) {
            #pragma unroll
            for (int rr = 0; rr < 2; rr++) {     // row-pair within frag (m row / m+8)
                #pragma unroll
                for (int hh = 0; hh < 2; hh++) { // element pair
                    float pa = P[2 * kp + hh][rr * 2 + 0];
                    float pb = P[2 * kp + hh][rr * 2 + 1];
                    __nv_bfloat16 ha = __float2bfloat16(pa);
                    __nv_bfloat16 hb = __float2bfloat16(pb);
                    aPh[kp][hh * 2 + rr] = pack_bf2(ha, hb);
                    aPl[kp][hh * 2 + rr] = pack_bf2(
                        __float2bfloat16(pa - __bfloat162float(ha)),
                        __float2bfloat16(pb - __bfloat162float(hb)));
                }
            }
        }

        // ---- O += P V (3-pass) ----
        const uint32_t vb_h = sb + (uint32_t)(AV + stg * V_STG + (lane & 15) * VLD) * 2;
        const uint32_t vb_l = vb_h + (uint32_t)V_PL * 2;
        #pragma unroll
        for (int kp = 0; kp < 2; kp++) {
            const uint32_t vkh = vb_h + (uint32_t)(kp * 16 * VLD) * 2;
            const uint32_t vkl = vb_l + (uint32_t)(kp * 16 * VLD) * 2;
            #pragma unroll
            for (int od = 0; od < 16; od++) {
                uint32_t bh[2], bl[2];
                ldsm2t(bh[0], bh[1], vkh + od * 16);
                ldsm2t(bl[0], bl[1], vkl + od * 16);
                mma16816(O[od], aPh[kp], bh);
                mma16816(O[od], aPh[kp], bl);
                mma16816(O[od], aPl[kp], bh);
            }
        }
        __syncthreads();
    }

    // ---- normalize + write ----
    float inv0 = 1.f / l0, inv1 = 1.f / l1;
    int row0 = b * SEQ + q0 + wid * 16 + (lane >> 2);
    float* o0 = g_att + (size_t)row0 * 2048 + h * 128 + (lane & 3) * 2;
    float* o1 = g_att + (size_t)(row0 + 8) * 2048 + h * 128 + (lane & 3) * 2;
    #pragma unroll
    for (int od = 0; od < 16; od++) {
        *reinterpret_cast<float2*>(o0 + od * 8) = make_float2(O[od][0] * inv0, O[od][1] * inv0);
        *reinterpret_cast<float2*>(o1 + od * 8) = make_float2(O[od][2] * inv1, O[od][3] * inv1);
    }
}

// ---------------- launch ----------------
static inline void conv(const float* in, __nv_bfloat16* hi, __nv_bfloat16* lo, int nelem)
{
    int n4 = nelem / 4;
    conv_split<<<(n4 + 255) / 256, 256>>>(in, hi, lo, n4);
}

extern "C" void kernel_launch(void* const* d_in, const int* in_sizes, int n_in,
                              void* d_out, int out_size)
{
    const float* x    = (const float*)d_in[0];
    const float* Wqa  = (const float*)d_in[1];
    const float* Wqb  = (const float*)d_in[2];
    const float* Wkva = (const float*)d_in[3];
    const float* Wkvb = (const float*)d_in[4];
    const float* Wout = (const float*)d_in[5];
    float* out = (float*)d_out;

    float *q1, *q, *ckv, *kv, *att;
    cudaGetSymbolAddress((void**)&q1,  g_q1);
    cudaGetSymbolAddress((void**)&q,   g_q);
    cudaGetSymbolAddress((void**)&ckv, g_ckv);
    cudaGetSymbolAddress((void**)&kv,  g_kv);
    cudaGetSymbolAddress((void**)&att, g_att);

    __nv_bfloat16 *xh, *xl, *q1h, *q1l, *ch, *cl, *ah, *al, *qbh, *qbl, *kvh, *kvl;
    __nv_bfloat16 *wqah, *wqal, *wqbh, *wqbl, *wkvah, *wkval, *wkvbh, *wkvbl, *wouth, *woutl;
    cudaGetSymbolAddress((void**)&xh,   g_xh);   cudaGetSymbolAddress((void**)&xl,   g_xl);
    cudaGetSymbolAddress((void**)&q1h,  g_q1h);  cudaGetSymbolAddress((void**)&q1l,  g_q1l);
    cudaGetSymbolAddress((void**)&ch,   g_ch);   cudaGetSymbolAddress((void**)&cl,   g_cl);
    cudaGetSymbolAddress((void**)&ah,   g_ah);   cudaGetSymbolAddress((void**)&al,   g_al);
    cudaGetSymbolAddress((void**)&qbh,  g_qbh);  cudaGetSymbolAddress((void**)&qbl,  g_qbl);
    cudaGetSymbolAddress((void**)&kvh,  g_kvh);  cudaGetSymbolAddress((void**)&kvl,  g_kvl);
    cudaGetSymbolAddress((void**)&wqah, g_Wqah); cudaGetSymbolAddress((void**)&wqal, g_Wqal);
    cudaGetSymbolAddress((void**)&wqbh, g_Wqbh); cudaGetSymbolAddress((void**)&wqbl, g_Wqbl);
    cudaGetSymbolAddress((void**)&wkvah, g_Wkvah); cudaGetSymbolAddress((void**)&wkval, g_Wkval);
    cudaGetSymbolAddress((void**)&wkvbh, g_Wkvbh); cudaGetSymbolAddress((void**)&wkvbl, g_Wkvbl);
    cudaGetSymbolAddress((void**)&wouth, g_Wouth); cudaGetSymbolAddress((void**)&woutl, g_Woutl);

    cudaFuncSetAttribute(gemm_hmma,
                         cudaFuncAttributeMaxDynamicSharedMemorySize, GEMM_SMEM);
    cudaFuncSetAttribute(attn_hmma,
                         cudaFuncAttributeMaxDynamicSharedMemorySize, ATT_SMEM);

    // ---- pre-split conversions (weights + x) ----
    conv(x,    xh,    xl,    NROWS * 2048);
    conv(Wqa,  wqah,  wqal,  2048 * 512);
    conv(Wqb,  wqbh,  wqbl,  512 * 3072);
    conv(Wkva, wkvah, wkval, 2048 * 576);
    conv(Wkvb, wkvbh, wkvbl, 512 * 4096);
    conv(Wout, wouth, woutl, 2048 * 2048);

    dim3 t(256);
    // q1 = x @ Wqa
    gemm_hmma<<<dim3(8, 32),  t, GEMM_SMEM>>>(xh, xl, 2048, wqah, wqal, 512,  q1, 512,  64);
    conv(q1, q1h, q1l, NROWS * 512);
    // q = q1 @ Wqb
    gemm_hmma<<<dim3(48, 32), t, GEMM_SMEM>>>(q1h, q1l, 512, wqbh, wqbl, 3072, q, 3072, 16);
    // ckv = x @ Wkva
    gemm_hmma<<<dim3(9, 32),  t, GEMM_SMEM>>>(xh, xl, 2048, wkvah, wkval, 576, ckv, 576, 64);
    // rope (fp32, in place)
    rope_kernel<<<4096, 544>>>();
    // hi/lo planes
    conv_split_ckv<<<(NROWS * 128 + 255) / 256, 256>>>();
    // kv = ckv_c @ Wkvb
    gemm_hmma<<<dim3(64, 32), t, GEMM_SMEM>>>(ch, cl, 512, wkvbh, wkvbl, 4096, kv, 4096, 16);
    // attention hi/lo planes
    conv(q,  qbh, qbl, NROWS * 3072);
    conv(kv, kvh, kvl, NROWS * 4096);
    conv_split_pe<<<(NROWS * 16 + 255) / 256, 256>>>();
    // flash attention (HMMA, 3-pass split)
    attn_hmma<<<dim3(SEQ / QT, NHEADS, 2), 256, ATT_SMEM>>>();
    conv(att, ah, al, NROWS * 2048);
    // out = att @ Wout
    gemm_hmma<<<dim3(32, 32), t, GEMM_SMEM>>>(ah, al, 2048, wouth, woutl, 2048, out, 2048, 64);
}

// round 10
// speedup vs baseline: 6.5204x; 1.0156x over previous
#include <cuda_runtime.h>
#include <cuda_bf16.h>
#include <math.h>
#include <stdint.h>

#define SEQ    2048
#define NROWS  4096
#define NHEADS 16

// ---------------- bf16 hi/lo planes (everything lives here) ----------------
__device__ __nv_bfloat16 g_xh[NROWS * 2048],  g_xl[NROWS * 2048];
__device__ __nv_bfloat16 g_q1h[NROWS * 512],  g_q1l[NROWS * 512];
__device__ __nv_bfloat16 g_ckvh[NROWS * 576], g_ckvl[NROWS * 576];
__device__ __nv_bfloat16 g_qbh[NROWS * 3072], g_qbl[NROWS * 3072];
__device__ __nv_bfloat16 g_kvh[NROWS * 4096], g_kvl[NROWS * 4096];
__device__ __nv_bfloat16 g_peh[NROWS * 64],   g_pel[NROWS * 64];
__device__ __nv_bfloat16 g_ah [NROWS * 2048], g_al [NROWS * 2048];
__device__ __nv_bfloat16 g_Wqah[2048 * 512],  g_Wqal[2048 * 512];
__device__ __nv_bfloat16 g_Wqbh[512 * 3072],  g_Wqbl[512 * 3072];
__device__ __nv_bfloat16 g_Wkvah[2048 * 576], g_Wkval[2048 * 576];
__device__ __nv_bfloat16 g_Wkvbh[512 * 4096], g_Wkvbl[512 * 4096];
__device__ __nv_bfloat16 g_Wouth[2048 * 2048], g_Woutl[2048 * 2048];

// ================= helpers =================
__device__ __forceinline__ uint32_t smem_u32(const void* p) {
    uint32_t a;
    asm("{ .reg .u64 t; cvta.to.shared.u64 t, %1; cvt.u32.u64 %0, t; }" : "=r"(a) : "l"(p));
    return a;
}
__device__ __forceinline__ void ldsm4(uint32_t& r0, uint32_t& r1, uint32_t& r2, uint32_t& r3,
                                      uint32_t addr) {
    asm volatile("ldmatrix.sync.aligned.m8n8.x4.shared.b16 {%0,%1,%2,%3}, [%4];"
                 : "=r"(r0), "=r"(r1), "=r"(r2), "=r"(r3) : "r"(addr));
}
__device__ __forceinline__ void ldsm2t(uint32_t& r0, uint32_t& r1, uint32_t addr) {
    asm volatile("ldmatrix.sync.aligned.m8n8.x2.trans.shared.b16 {%0,%1}, [%2];"
                 : "=r"(r0), "=r"(r1) : "r"(addr));
}
__device__ __forceinline__ void mma16816(float* c, const uint32_t* a, const uint32_t* b) {
    asm volatile(
        "mma.sync.aligned.m16n8k16.row.col.f32.bf16.bf16.f32 "
        "{%0,%1,%2,%3}, {%4,%5,%6,%7}, {%8,%9}, {%0,%1,%2,%3};"
        : "+f"(c[0]), "+f"(c[1]), "+f"(c[2]), "+f"(c[3])
        : "r"(a[0]), "r"(a[1]), "r"(a[2]), "r"(a[3]), "r"(b[0]), "r"(b[1]));
}
__device__ __forceinline__ void cp16(uint32_t saddr, const void* g) {
    asm volatile("cp.async.ca.shared.global [%0], [%1], 16;" :: "r"(saddr), "l"(g));
}
#define CP_COMMIT() asm volatile("cp.async.commit_group;" ::: "memory")
#define CP_WAIT(n)  asm volatile("cp.async.wait_group %0;" :: "n"(n) : "memory")

__device__ __forceinline__ uint32_t pack_bf2(__nv_bfloat16 a, __nv_bfloat16 b) {
    __nv_bfloat162 t(a, b);
    return *reinterpret_cast<uint32_t*>(&t);
}
// split a pair of floats into packed hi / packed lo bf16x2
__device__ __forceinline__ void split2(float a, float b, uint32_t& h, uint32_t& l) {
    __nv_bfloat16 ha = __float2bfloat16(a), hb = __float2bfloat16(b);
    h = pack_bf2(ha, hb);
    l = pack_bf2(__float2bfloat16(a - __bfloat162float(ha)),
                 __float2bfloat16(b - __bfloat162float(hb)));
}
__device__ __forceinline__ void cvt_split4(float4 v, uint2& hi, uint2& lo) {
    split2(v.x, v.y, hi.x, lo.x);
    split2(v.z, v.w, hi.y, lo.y);
}

// ---------------- input conversion ----------------
__global__ void conv_split(const float* __restrict__ in,
                           __nv_bfloat16* __restrict__ hi,
                           __nv_bfloat16* __restrict__ lo, int n4)
{
    int i = blockIdx.x * blockDim.x + threadIdx.x;
    if (i < n4) {
        float4 v = reinterpret_cast<const float4*>(in)[i];
        uint2 h, l; cvt_split4(v, h, l);
        reinterpret_cast<uint2*>(hi)[i] = h;
        reinterpret_cast<uint2*>(lo)[i] = l;
    }
}

// ================= HMMA bf16-split GEMM =================
// C = (Ah+Al)(Bh+Bl), 3-pass. CTA 128x64, K-chunk 32, 256 thr.
// Output: fp32 C (if Cf) and/or bf16 hi/lo planes (if Ch).
#define KCH 32
#define ALD 40
#define BLD 72
#define A_PLANE (128 * ALD)
#define B_PLANE (KCH * BLD)
#define OFF_AH 0
#define OFF_AL A_PLANE
#define OFF_BH (2 * A_PLANE)
#define OFF_BL (2 * A_PLANE + B_PLANE)
#define STAGE_E (2 * A_PLANE + 2 * B_PLANE)
#define GEMM_SMEM (2 * STAGE_E * 2)

__global__ __launch_bounds__(256) void gemm_hmma(
    const __nv_bfloat16* __restrict__ Ah, const __nv_bfloat16* __restrict__ Al, int lda,
    const __nv_bfloat16* __restrict__ Bh, const __nv_bfloat16* __restrict__ Bl, int ldb,
    float* __restrict__ Cf, int ldc,
    __nv_bfloat16* __restrict__ Ch, __nv_bfloat16* __restrict__ Cl, int ldh,
    int nchunks)
{
    extern __shared__ __nv_bfloat16 sm[];
    const int tid  = threadIdx.x;
    const int wid  = tid >> 5;
    const int lane = tid & 31;
    const int m0 = blockIdx.y * 128;
    const int n0 = blockIdx.x * 64;
    const int mw = (wid & 3) * 32;
    const int nw = (wid >> 2) * 32;
    const uint32_t sm_base = smem_u32(sm);

    float acc[2][4][4];
    #pragma unroll
    for (int i = 0; i < 2; i++)
        #pragma unroll
        for (int j = 0; j < 4; j++)
            #pragma unroll
            for (int e = 0; e < 4; e++) acc[i][j][e] = 0.f;

    const int ar  = tid >> 1;
    const int as  = (tid & 1) * 2;
    const int br  = tid >> 3;
    const int bs  = tid & 7;

    const uint32_t aRow = lane & 15;
    const uint32_t aCol = (lane >> 4) * 8;
    const uint32_t aHoff = (uint32_t)(OFF_AH + (mw + aRow) * ALD + aCol) * 2;
    const uint32_t aLoff = (uint32_t)(OFF_AL + (mw + aRow) * ALD + aCol) * 2;
    const uint32_t bHoff = (uint32_t)(OFF_BH + (lane & 15) * BLD + nw) * 2;
    const uint32_t bLoff = (uint32_t)(OFF_BL + (lane & 15) * BLD + nw) * 2;

    auto load_stage = [&](int stg, int ch) {
        const uint32_t sb = sm_base + (uint32_t)stg * (STAGE_E * 2);
        const int k0 = ch * KCH;
        #pragma unroll
        for (int s = 0; s < 2; s++) {
            int seg = as + s;
            cp16(sb + (uint32_t)(OFF_AH + ar * ALD + seg * 8) * 2,
                 Ah + (size_t)(m0 + ar) * lda + k0 + seg * 8);
            cp16(sb + (uint32_t)(OFF_AL + ar * ALD + seg * 8) * 2,
                 Al + (size_t)(m0 + ar) * lda + k0 + seg * 8);
        }
        cp16(sb + (uint32_t)(OFF_BH + br * BLD + bs * 8) * 2,
             Bh + (size_t)(k0 + br) * ldb + n0 + bs * 8);
        cp16(sb + (uint32_t)(OFF_BL + br * BLD + bs * 8) * 2,
             Bl + (size_t)(k0 + br) * ldb + n0 + bs * 8);
    };

    load_stage(0, 0);
    CP_COMMIT();

    for (int ch = 0; ch < nchunks; ch++) {
        const int stg = ch & 1;
        if (ch + 1 < nchunks) {
            load_stage(stg ^ 1, ch + 1);
            CP_COMMIT();
            CP_WAIT(1);
        } else {
            CP_WAIT(0);
        }
        __syncthreads();

        const uint32_t sb = sm_base + (uint32_t)stg * (STAGE_E * 2);
        #pragma unroll
        for (int ks = 0; ks < 2; ks++) {
            const uint32_t kA = (uint32_t)(ks * 16) * 2;
            const uint32_t kB = (uint32_t)(ks * 16 * BLD) * 2;
            uint32_t aH[2][4], aL[2][4], bH[4][2], bL[4][2];
            #pragma unroll
            for (int mi = 0; mi < 2; mi++) {
                uint32_t off = (uint32_t)(mi * 16 * ALD) * 2 + kA;
                ldsm4(aH[mi][0], aH[mi][1], aH[mi][2], aH[mi][3], sb + aHoff + off);
                ldsm4(aL[mi][0], aL[mi][1], aL[mi][2], aL[mi][3], sb + aLoff + off);
            }
            #pragma unroll
            for (int ni = 0; ni < 4; ni++) {
                uint32_t off = kB + (uint32_t)(ni * 8) * 2;
                ldsm2t(bH[ni][0], bH[ni][1], sb + bHoff + off);
                ldsm2t(bL[ni][0], bL[ni][1], sb + bLoff + off);
            }
            #pragma unroll
            for (int mi = 0; mi < 2; mi++)
                #pragma unroll
                for (int ni = 0; ni < 4; ni++) {
                    mma16816(acc[mi][ni], aH[mi], bH[ni]);
                    mma16816(acc[mi][ni], aH[mi], bL[ni]);
                    mma16816(acc[mi][ni], aL[mi], bH[ni]);
                }
        }
        __syncthreads();
    }

    const int cr = lane >> 2;
    const int cc = (lane & 3) * 2;
    #pragma unroll
    for (int mi = 0; mi < 2; mi++)
        #pragma unroll
        for (int ni = 0; ni < 4; ni++) {
            int row = m0 + mw + mi * 16 + cr;
            int col = n0 + nw + ni * 8 + cc;
            if (Cf) {
                *reinterpret_cast<float2*>(Cf + (size_t)row * ldc + col) =
                    make_float2(acc[mi][ni][0], acc[mi][ni][1]);
                *reinterpret_cast<float2*>(Cf + (size_t)(row + 8) * ldc + col) =
                    make_float2(acc[mi][ni][2], acc[mi][ni][3]);
            }
            if (Ch) {
                uint32_t h0, l0, h1, l1;
                split2(acc[mi][ni][0], acc[mi][ni][1], h0, l0);
                split2(acc[mi][ni][2], acc[mi][ni][3], h1, l1);
                *reinterpret_cast<uint32_t*>(Ch + (size_t)row * ldh + col)       = h0;
                *reinterpret_cast<uint32_t*>(Cl + (size_t)row * ldh + col)       = l0;
                *reinterpret_cast<uint32_t*>(Ch + (size_t)(row + 8) * ldh + col) = h1;
                *reinterpret_cast<uint32_t*>(Cl + (size_t)(row + 8) * ldh + col) = l1;
            }
        }
}

// ---------------- RoPE on hi/lo planes ----------------
// warps 0-15: q_pe per head (reconstruct hi+lo, rotate, re-split in place)
// warp 16:    k_pe -> write split result to g_peh/g_pel
__global__ void rope_kernel()
{
    const int row  = blockIdx.x;
    const int pos  = row & (SEQ - 1);
    const int warp = threadIdx.x >> 5;
    const int lane = threadIdx.x & 31;

    float theta = __powf(10000.0f, -(float)lane * (1.0f / 32.0f));
    float ang = (float)pos * theta;
    float s, c;
    sincosf(ang, &s, &c);

    if (warp < 16) {
        size_t off = (size_t)row * 3072 + warp * 192 + 128 + 2 * lane;
        uint32_t hv = *reinterpret_cast<uint32_t*>(g_qbh + off);
        uint32_t lv = *reinterpret_cast<uint32_t*>(g_qbl + off);
        __nv_bfloat162 h2 = *reinterpret_cast<__nv_bfloat162*>(&hv);
        __nv_bfloat162 l2 = *reinterpret_cast<__nv_bfloat162*>(&lv);
        float x1 = __bfloat162float(h2.x) + __bfloat162float(l2.x);
        float x2 = __bfloat162float(h2.y) + __bfloat162float(l2.y);
        float o1 = x1 * c - x2 * s;
        float o2 = x1 * s + x2 * c;
        uint32_t oh, ol;
        split2(o1, o2, oh, ol);
        *reinterpret_cast<uint32_t*>(g_qbh + off) = oh;
        *reinterpret_cast<uint32_t*>(g_qbl + off) = ol;
    } else {
        size_t off = (size_t)row * 576 + 512 + 2 * lane;
        uint32_t hv = *reinterpret_cast<uint32_t*>(g_ckvh + off);
        uint32_t lv = *reinterpret_cast<uint32_t*>(g_ckvl + off);
        __nv_bfloat162 h2 = *reinterpret_cast<__nv_bfloat162*>(&hv);
        __nv_bfloat162 l2 = *reinterpret_cast<__nv_bfloat162*>(&lv);
        float x1 = __bfloat162float(h2.x) + __bfloat162float(l2.x);
        float x2 = __bfloat162float(h2.y) + __bfloat162float(l2.y);
        float o1 = x1 * c - x2 * s;
        float o2 = x1 * s + x2 * c;
        uint32_t oh, ol;
        split2(o1, o2, oh, ol);
        size_t po = (size_t)row * 64 + 2 * lane;
        *reinterpret_cast<uint32_t*>(g_peh + po) = oh;
        *reinterpret_cast<uint32_t*>(g_pel + po) = ol;
    }
}

// ================= HMMA flash attention, bf16 3-pass split =================
#define QT 128
#define KT 32
#define QLD 200
#define KLD 200
#define VLD 136
#define AQ_H 0
#define AQ_L (QT * QLD)
#define AK   (2 * QT * QLD)
#define K_STG (2 * KT * KLD)
#define K_PL  (KT * KLD)
#define AV   (AK + 2 * K_STG)
#define V_STG (2 * KT * VLD)
#define V_PL  (KT * VLD)
#define ATT_E (AV + 2 * V_STG)
#define ATT_SMEM (ATT_E * 2)

__global__ __launch_bounds__(256, 1) void attn_hmma()
{
    extern __shared__ __nv_bfloat16 sm[];
    const int tid = threadIdx.x, wid = tid >> 5, lane = tid & 31;
    const int b = blockIdx.z, h = blockIdx.y;
    const int q0 = blockIdx.x * QT;
    const uint32_t sb = smem_u32(sm);
    const float scale = 0.07216878364870323f;   // 1/sqrt(192)

    {
        int r = tid >> 1;
        size_t row = (size_t)(b * SEQ + q0 + r) * 3072 + h * 192;
        const __nv_bfloat16* srch = g_qbh + row;
        const __nv_bfloat16* srcl = g_qbl + row;
        uint32_t dsth = sb + (uint32_t)(AQ_H + r * QLD) * 2;
        uint32_t dstl = sb + (uint32_t)(AQ_L + r * QLD) * 2;
        #pragma unroll
        for (int s = 0; s < 12; s++) {
            int seg = (tid & 1) * 12 + s;
            cp16(dsth + seg * 16, srch + seg * 8);
            cp16(dstl + seg * 16, srcl + seg * 8);
        }
    }

    auto load_kv = [&](int stg, int kt0) {
        int r = tid >> 3;
        size_t row = (size_t)(b * SEQ + kt0 + r);
        const __nv_bfloat16* knh = g_kvh + row * 4096 + h * 256;
        const __nv_bfloat16* knl = g_kvl + row * 4096 + h * 256;
        const __nv_bfloat16* peh = g_peh + row * 64;
        const __nv_bfloat16* pel = g_pel + row * 64;
        uint32_t kdh = sb + (uint32_t)(AK + stg * K_STG + r * KLD) * 2;
        uint32_t kdl = kdh + (uint32_t)K_PL * 2;
        uint32_t vdh = sb + (uint32_t)(AV + stg * V_STG + r * VLD) * 2;
        uint32_t vdl = vdh + (uint32_t)V_PL * 2;
        #pragma unroll
        for (int s = 0; s < 10; s++) {
            int seg = (tid & 7) * 10 + s;
            if (seg < 16)      cp16(kdh + seg * 16, knh + seg * 8);
            else if (seg < 24) cp16(kdh + seg * 16, peh + (seg - 16) * 8);
            else if (seg < 40) cp16(kdl + (seg - 24) * 16, knl + (seg - 24) * 8);
            else if (seg < 48) cp16(kdl + (seg - 24) * 16, pel + (seg - 40) * 8);
            else if (seg < 64) cp16(vdh + (seg - 48) * 16, knh + 128 + (seg - 48) * 8);
            else               cp16(vdl + (seg - 64) * 16, knl + 128 + (seg - 64) * 8);
        }
    };

    load_kv(0, 0);
    CP_COMMIT();

    const int ntiles = q0 / KT + QT / KT;
    float m0 = -INFINITY, m1 = -INFINITY, l0 = 0.f, l1 = 0.f;
    float O[16][4];
    #pragma unroll
    for (int od = 0; od < 16; od++)
        #pragma unroll
        for (int e = 0; e < 4; e++) O[od][e] = 0.f;

    const uint32_t qb_h = sb + (uint32_t)(AQ_H + (wid * 16 + (lane & 15)) * QLD + (lane >> 4) * 8) * 2;
    const uint32_t qb_l = qb_h + (uint32_t)(QT * QLD) * 2;

    for (int t = 0; t < ntiles; t++) {
        const int stg = t & 1;
        if (t + 1 < ntiles) {
            load_kv(stg ^ 1, (t + 1) * KT);
            CP_COMMIT();
            CP_WAIT(1);
        } else {
            CP_WAIT(0);
        }
        __syncthreads();

        float S[4][4];
        #pragma unroll
        for (int g = 0; g < 4; g++)
            #pragma unroll
            for (int e = 0; e < 4; e++) S[g][e] = 0.f;

        const uint32_t kb_h = sb + (uint32_t)(AK + stg * K_STG + (lane & 15) * KLD + (lane >> 4) * 8) * 2;
        const uint32_t kb_l = kb_h + (uint32_t)K_PL * 2;
        #pragma unroll
        for (int ks = 0; ks < 12; ks++) {
            uint32_t aH[4], aL[4];
            ldsm4(aH[0], aH[1], aH[2], aH[3], qb_h + ks * 32);
            ldsm4(aL[0], aL[1], aL[2], aL[3], qb_l + ks * 32);
            #pragma unroll
            for (int np = 0; np < 2; np++) {
                uint32_t off = (uint32_t)(np * 16 * KLD) * 2 + ks * 32;
                uint32_t h0, h1, h2, h3, l0r, l1r, l2r, l3r;
                ldsm4(h0, h1, h2, h3, kb_h + off);
                ldsm4(l0r, l1r, l2r, l3r, kb_l + off);
                uint32_t bh0[2] = {h0, h2},  bh1[2] = {h1, h3};
                uint32_t bl0[2] = {l0r, l2r}, bl1[2] = {l1r, l3r};
                mma16816(S[np * 2],     aH, bh0);
                mma16816(S[np * 2],     aH, bl0);
                mma16816(S[np * 2],     aL, bh0);
                mma16816(S[np * 2 + 1], aH, bh1);
                mma16816(S[np * 2 + 1], aH, bl1);
                mma16816(S[np * 2 + 1], aL, bh1);
            }
        }

        const int mrow0 = q0 + wid * 16 + (lane >> 2);
        const int kcol0 = t * KT + (lane & 3) * 2;
        const bool needmask = (t * KT + KT - 1) > (q0 + wid * 16);
        if (needmask) {
            #pragma unroll
            for (int g = 0; g < 4; g++) {
                int kc = kcol0 + g * 8;
                S[g][0] = (kc     <= mrow0)     ? S[g][0] * scale : -INFINITY;
                S[g][1] = (kc + 1 <= mrow0)     ? S[g][1] * scale : -INFINITY;
                S[g][2] = (kc     <= mrow0 + 8) ? S[g][2] * scale : -INFINITY;
                S[g][3] = (kc + 1 <= mrow0 + 8) ? S[g][3] * scale : -INFINITY;
            }
        } else {
            #pragma unroll
            for (int g = 0; g < 4; g++)
                #pragma unroll
                for (int e = 0; e < 4; e++) S[g][e] *= scale;
        }

        float tm0 = -INFINITY, tm1 = -INFINITY;
        #pragma unroll
        for (int g = 0; g < 4; g++) {
            tm0 = fmaxf(tm0, fmaxf(S[g][0], S[g][1]));
            tm1 = fmaxf(tm1, fmaxf(S[g][2], S[g][3]));
        }
        tm0 = fmaxf(tm0, __shfl_xor_sync(0xffffffffu, tm0, 1));
        tm0 = fmaxf(tm0, __shfl_xor_sync(0xffffffffu, tm0, 2));
        tm1 = fmaxf(tm1, __shfl_xor_sync(0xffffffffu, tm1, 1));
        tm1 = fmaxf(tm1, __shfl_xor_sync(0xffffffffu, tm1, 2));

        float mn0 = fmaxf(m0, tm0), mn1 = fmaxf(m1, tm1);
        float al0 = __expf(m0 - mn0), al1 = __expf(m1 - mn1);
        m0 = mn0; m1 = mn1;

        float P[4][4];
        float s0 = 0.f, s1 = 0.f;
        #pragma unroll
        for (int g = 0; g < 4; g++) {
            P[g][0] = __expf(S[g][0] - m0); s0 += P[g][0];
            P[g][1] = __expf(S[g][1] - m0); s0 += P[g][1];
            P[g][2] = __expf(S[g][2] - m1); s1 += P[g][2];
            P[g][3] = __expf(S[g][3] - m1); s1 += P[g][3];
        }
        s0 += __shfl_xor_sync(0xffffffffu, s0, 1);
        s0 += __shfl_xor_sync(0xffffffffu, s0, 2);
        s1 += __shfl_xor_sync(0xffffffffu, s1, 1);
        s1 += __shfl_xor_sync(0xffffffffu, s1, 2);
        l0 = l0 * al0 + s0;
        l1 = l1 * al1 + s1;

        #pragma unroll
        for (int od = 0; od < 16; od++) {
            O[od][0] *= al0; O[od][1] *= al0;
            O[od][2] *= al1; O[od][3] *= al1;
        }

        uint32_t aPh[2][4], aPl[2][4];
        #pragma unroll
        for (int kp = 0; kp < 2; kp++) {
            #pragma unroll
            for (int rr = 0; rr < 2; rr++) {
                #pragma unroll
                for (int hh = 0; hh < 2; hh++) {
                    float pa = P[2 * kp + hh][rr * 2 + 0];
                    float pb = P[2 * kp + hh][rr * 2 + 1];
                    split2(pa, pb, aPh[kp][hh * 2 + rr], aPl[kp][hh * 2 + rr]);
                }
            }
        }

        const uint32_t vb_h = sb + (uint32_t)(AV + stg * V_STG + (lane & 15) * VLD) * 2;
        const uint32_t vb_l = vb_h + (uint32_t)V_PL * 2;
        #pragma unroll
        for (int kp = 0; kp < 2; kp++) {
            const uint32_t vkh = vb_h + (uint32_t)(kp * 16 * VLD) * 2;
            const uint32_t vkl = vb_l + (uint32_t)(kp * 16 * VLD) * 2;
            #pragma unroll
            for (int od = 0; od < 16; od++) {
                uint32_t bh[2], bl[2];
                ldsm2t(bh[0], bh[1], vkh + od * 16);
                ldsm2t(bl[0], bl[1], vkl + od * 16);
                mma16816(O[od], aPh[kp], bh);
                mma16816(O[od], aPh[kp], bl);
                mma16816(O[od], aPl[kp], bh);
            }
        }
        __syncthreads();
    }

    // ---- normalize + split write to ah/al planes ----
    float inv0 = 1.f / l0, inv1 = 1.f / l1;
    int row0 = b * SEQ + q0 + wid * 16 + (lane >> 2);
    size_t o0 = (size_t)row0 * 2048 + h * 128 + (lane & 3) * 2;
    size_t o1 = (size_t)(row0 + 8) * 2048 + h * 128 + (lane & 3) * 2;
    #pragma unroll
    for (int od = 0; od < 16; od++) {
        uint32_t h0, l0p, h1, l1p;
        split2(O[od][0] * inv0, O[od][1] * inv0, h0, l0p);
        split2(O[od][2] * inv1, O[od][3] * inv1, h1, l1p);
        *reinterpret_cast<uint32_t*>(g_ah + o0 + od * 8) = h0;
        *reinterpret_cast<uint32_t*>(g_al + o0 + od * 8) = l0p;
        *reinterpret_cast<uint32_t*>(g_ah + o1 + od * 8) = h1;
        *reinterpret_cast<uint32_t*>(g_al + o1 + od * 8) = l1p;
    }
}

// ---------------- launch ----------------
static inline void conv(const float* in, __nv_bfloat16* hi, __nv_bfloat16* lo, int nelem)
{
    int n4 = nelem / 4;
    conv_split<<<(n4 + 255) / 256, 256>>>(in, hi, lo, n4);
}

extern "C" void kernel_launch(void* const* d_in, const int* in_sizes, int n_in,
                              void* d_out, int out_size)
{
    const float* x    = (const float*)d_in[0];
    const float* Wqa  = (const float*)d_in[1];
    const float* Wqb  = (const float*)d_in[2];
    const float* Wkva = (const float*)d_in[3];
    const float* Wkvb = (const float*)d_in[4];
    const float* Wout = (const float*)d_in[5];
    float* out = (float*)d_out;

    __nv_bfloat16 *xh, *xl, *q1h, *q1l, *ckvh, *ckvl, *qbh, *qbl, *kvh, *kvl, *ah, *al;
    __nv_bfloat16 *wqah, *wqal, *wqbh, *wqbl, *wkvah, *wkval, *wkvbh, *wkvbl, *wouth, *woutl;
    cudaGetSymbolAddress((void**)&xh,   g_xh);   cudaGetSymbolAddress((void**)&xl,   g_xl);
    cudaGetSymbolAddress((void**)&q1h,  g_q1h);  cudaGetSymbolAddress((void**)&q1l,  g_q1l);
    cudaGetSymbolAddress((void**)&ckvh, g_ckvh); cudaGetSymbolAddress((void**)&ckvl, g_ckvl);
    cudaGetSymbolAddress((void**)&qbh,  g_qbh);  cudaGetSymbolAddress((void**)&qbl,  g_qbl);
    cudaGetSymbolAddress((void**)&kvh,  g_kvh);  cudaGetSymbolAddress((void**)&kvl,  g_kvl);
    cudaGetSymbolAddress((void**)&ah,   g_ah);   cudaGetSymbolAddress((void**)&al,   g_al);
    cudaGetSymbolAddress((void**)&wqah, g_Wqah); cudaGetSymbolAddress((void**)&wqal, g_Wqal);
    cudaGetSymbolAddress((void**)&wqbh, g_Wqbh); cudaGetSymbolAddress((void**)&wqbl, g_Wqbl);
    cudaGetSymbolAddress((void**)&wkvah, g_Wkvah); cudaGetSymbolAddress((void**)&wkval, g_Wkval);
    cudaGetSymbolAddress((void**)&wkvbh, g_Wkvbh); cudaGetSymbolAddress((void**)&wkvbl, g_Wkvbl);
    cudaGetSymbolAddress((void**)&wouth, g_Wouth); cudaGetSymbolAddress((void**)&woutl, g_Woutl);

    cudaFuncSetAttribute(gemm_hmma,
                         cudaFuncAttributeMaxDynamicSharedMemorySize, GEMM_SMEM);
    cudaFuncSetAttribute(attn_hmma,
                         cudaFuncAttributeMaxDynamicSharedMemorySize, ATT_SMEM);

    // ---- input conversions ----
    conv(x,    xh,    xl,    NROWS * 2048);
    conv(Wqa,  wqah,  wqal,  2048 * 512);
    conv(Wqb,  wqbh,  wqbl,  512 * 3072);
    conv(Wkva, wkvah, wkval, 2048 * 576);
    conv(Wkvb, wkvbh, wkvbl, 512 * 4096);
    conv(Wout, wouth, woutl, 2048 * 2048);

    dim3 t(256);
    // q1 = x @ Wqa -> hi/lo planes only
    gemm_hmma<<<dim3(8, 32),  t, GEMM_SMEM>>>(xh, xl, 2048, wqah, wqal, 512,
                                              nullptr, 0, q1h, q1l, 512, 64);
    // q = q1 @ Wqb -> hi/lo planes
    gemm_hmma<<<dim3(48, 32), t, GEMM_SMEM>>>(q1h, q1l, 512, wqbh, wqbl, 3072,
                                              nullptr, 0, qbh, qbl, 3072, 16);
    // ckv = x @ Wkva -> hi/lo planes (full 576 width)
    gemm_hmma<<<dim3(9, 32),  t, GEMM_SMEM>>>(xh, xl, 2048, wkvah, wkval, 576,
                                              nullptr, 0, ckvh, ckvl, 576, 64);
    // rope on hi/lo planes (q_pe in place; k_pe -> pe planes)
    rope_kernel<<<4096, 544>>>();
    // kv = ckv[:, :512] @ Wkvb -> hi/lo planes
    gemm_hmma<<<dim3(64, 32), t, GEMM_SMEM>>>(ckvh, ckvl, 576, wkvbh, wkvbl, 4096,
                                              nullptr, 0, kvh, kvl, 4096, 16);
    // flash attention -> ah/al planes
    attn_hmma<<<dim3(SEQ / QT, NHEADS, 2), 256, ATT_SMEM>>>();
    // out = att @ Wout -> fp32 output
    gemm_hmma<<<dim3(32, 32), t, GEMM_SMEM>>>(ah, al, 2048, wouth, woutl, 2048,
                                              out, 2048, nullptr, nullptr, 0, 64);
}

// round 11
// speedup vs baseline: 6.6859x; 1.0254x over previous
#include <cuda_runtime.h>
#include <cuda_bf16.h>
#include <math.h>
#include <stdint.h>

#define SEQ    2048
#define NROWS  4096
#define NHEADS 16

// ---------------- bf16 hi/lo planes ----------------
__device__ __nv_bfloat16 g_xh[NROWS * 2048],  g_xl[NROWS * 2048];
__device__ __nv_bfloat16 g_q1h[NROWS * 512],  g_q1l[NROWS * 512];
__device__ __nv_bfloat16 g_ckvh[NROWS * 576], g_ckvl[NROWS * 576];
__device__ __nv_bfloat16 g_qbh[NROWS * 3072], g_qbl[NROWS * 3072];
__device__ __nv_bfloat16 g_kvh[NROWS * 4096], g_kvl[NROWS * 4096];
__device__ __nv_bfloat16 g_peh[NROWS * 64],   g_pel[NROWS * 64];
__device__ __nv_bfloat16 g_ah [NROWS * 2048], g_al [NROWS * 2048];
__device__ __nv_bfloat16 g_Wqah[2048 * 512],  g_Wqal[2048 * 512];
__device__ __nv_bfloat16 g_Wqbh[512 * 3072],  g_Wqbl[512 * 3072];
__device__ __nv_bfloat16 g_Wkvah[2048 * 576], g_Wkval[2048 * 576];
__device__ __nv_bfloat16 g_Wkvbh[512 * 4096], g_Wkvbl[512 * 4096];
__device__ __nv_bfloat16 g_Wouth[2048 * 2048], g_Woutl[2048 * 2048];

// ================= helpers =================
__device__ __forceinline__ uint32_t smem_u32(const void* p) {
    uint32_t a;
    asm("{ .reg .u64 t; cvta.to.shared.u64 t, %1; cvt.u32.u64 %0, t; }" : "=r"(a) : "l"(p));
    return a;
}
__device__ __forceinline__ void ldsm4(uint32_t& r0, uint32_t& r1, uint32_t& r2, uint32_t& r3,
                                      uint32_t addr) {
    asm volatile("ldmatrix.sync.aligned.m8n8.x4.shared.b16 {%0,%1,%2,%3}, [%4];"
                 : "=r"(r0), "=r"(r1), "=r"(r2), "=r"(r3) : "r"(addr));
}
__device__ __forceinline__ void ldsm4t(uint32_t& r0, uint32_t& r1, uint32_t& r2, uint32_t& r3,
                                       uint32_t addr) {
    asm volatile("ldmatrix.sync.aligned.m8n8.x4.trans.shared.b16 {%0,%1,%2,%3}, [%4];"
                 : "=r"(r0), "=r"(r1), "=r"(r2), "=r"(r3) : "r"(addr));
}
__device__ __forceinline__ void mma16816(float* c, const uint32_t* a, const uint32_t* b) {
    asm volatile(
        "mma.sync.aligned.m16n8k16.row.col.f32.bf16.bf16.f32 "
        "{%0,%1,%2,%3}, {%4,%5,%6,%7}, {%8,%9}, {%0,%1,%2,%3};"
        : "+f"(c[0]), "+f"(c[1]), "+f"(c[2]), "+f"(c[3])
        : "r"(a[0]), "r"(a[1]), "r"(a[2]), "r"(a[3]), "r"(b[0]), "r"(b[1]));
}
__device__ __forceinline__ void cp16(uint32_t saddr, const void* g) {
    asm volatile("cp.async.ca.shared.global [%0], [%1], 16;" :: "r"(saddr), "l"(g));
}
#define CP_COMMIT() asm volatile("cp.async.commit_group;" ::: "memory")
#define CP_WAIT(n)  asm volatile("cp.async.wait_group %0;" :: "n"(n) : "memory")

__device__ __forceinline__ uint32_t pack_bf2(__nv_bfloat16 a, __nv_bfloat16 b) {
    __nv_bfloat162 t(a, b);
    return *reinterpret_cast<uint32_t*>(&t);
}
__device__ __forceinline__ void split2(float a, float b, uint32_t& h, uint32_t& l) {
    __nv_bfloat16 ha = __float2bfloat16(a), hb = __float2bfloat16(b);
    h = pack_bf2(ha, hb);
    l = pack_bf2(__float2bfloat16(a - __bfloat162float(ha)),
                 __float2bfloat16(b - __bfloat162float(hb)));
}
__device__ __forceinline__ void cvt_split4(float4 v, uint2& hi, uint2& lo) {
    split2(v.x, v.y, hi.x, lo.x);
    split2(v.z, v.w, hi.y, lo.y);
}

// ---------------- input conversion ----------------
__global__ void conv_split(const float* __restrict__ in,
                           __nv_bfloat16* __restrict__ hi,
                           __nv_bfloat16* __restrict__ lo, int n4)
{
    int i = blockIdx.x * blockDim.x + threadIdx.x;
    if (i < n4) {
        float4 v = reinterpret_cast<const float4*>(in)[i];
        uint2 h, l; cvt_split4(v, h, l);
        reinterpret_cast<uint2*>(hi)[i] = h;
        reinterpret_cast<uint2*>(lo)[i] = l;
    }
}

// ================= HMMA bf16-split GEMM =================
#define KCH 32
#define ALD 40
#define BLD 72
#define A_PLANE (128 * ALD)
#define B_PLANE (KCH * BLD)
#define OFF_AH 0
#define OFF_AL A_PLANE
#define OFF_BH (2 * A_PLANE)
#define OFF_BL (2 * A_PLANE + B_PLANE)
#define STAGE_E (2 * A_PLANE + 2 * B_PLANE)
#define GEMM_SMEM (2 * STAGE_E * 2)

__global__ __launch_bounds__(256) void gemm_hmma(
    const __nv_bfloat16* __restrict__ Ah, const __nv_bfloat16* __restrict__ Al, int lda,
    const __nv_bfloat16* __restrict__ Bh, const __nv_bfloat16* __restrict__ Bl, int ldb,
    float* __restrict__ Cf, int ldc,
    __nv_bfloat16* __restrict__ Ch, __nv_bfloat16* __restrict__ Cl, int ldh,
    int nchunks)
{
    extern __shared__ __nv_bfloat16 sm[];
    const int tid  = threadIdx.x;
    const int wid  = tid >> 5;
    const int lane = tid & 31;
    const int m0 = blockIdx.y * 128;
    const int n0 = blockIdx.x * 64;
    const int mw = (wid & 3) * 32;
    const int nw = (wid >> 2) * 32;
    const uint32_t sm_base = smem_u32(sm);

    float acc[2][4][4];
    #pragma unroll
    for (int i = 0; i < 2; i++)
        #pragma unroll
        for (int j = 0; j < 4; j++)
            #pragma unroll
            for (int e = 0; e < 4; e++) acc[i][j][e] = 0.f;

    const int ar  = tid >> 1;
    const int as  = (tid & 1) * 2;
    const int br  = tid >> 3;
    const int bs  = tid & 7;

    const uint32_t aRow = lane & 15;
    const uint32_t aCol = (lane >> 4) * 8;
    const uint32_t aHoff = (uint32_t)(OFF_AH + (mw + aRow) * ALD + aCol) * 2;
    const uint32_t aLoff = (uint32_t)(OFF_AL + (mw + aRow) * ALD + aCol) * 2;
    // x4.trans B addressing: lanes 0-15 -> k-rows at col nw, lanes 16-31 -> k-rows at col nw+8
    const uint32_t bHoff = (uint32_t)(OFF_BH + (lane & 15) * BLD + nw + (lane >> 4) * 8) * 2;
    const uint32_t bLoff = (uint32_t)(OFF_BL + (lane & 15) * BLD + nw + (lane >> 4) * 8) * 2;

    auto load_stage = [&](int stg, int ch) {
        const uint32_t sb = sm_base + (uint32_t)stg * (STAGE_E * 2);
        const int k0 = ch * KCH;
        #pragma unroll
        for (int s = 0; s < 2; s++) {
            int seg = as + s;
            cp16(sb + (uint32_t)(OFF_AH + ar * ALD + seg * 8) * 2,
                 Ah + (size_t)(m0 + ar) * lda + k0 + seg * 8);
            cp16(sb + (uint32_t)(OFF_AL + ar * ALD + seg * 8) * 2,
                 Al + (size_t)(m0 + ar) * lda + k0 + seg * 8);
        }
        cp16(sb + (uint32_t)(OFF_BH + br * BLD + bs * 8) * 2,
             Bh + (size_t)(k0 + br) * ldb + n0 + bs * 8);
        cp16(sb + (uint32_t)(OFF_BL + br * BLD + bs * 8) * 2,
             Bl + (size_t)(k0 + br) * ldb + n0 + bs * 8);
    };

    load_stage(0, 0);
    CP_COMMIT();

    for (int ch = 0; ch < nchunks; ch++) {
        const int stg = ch & 1;
        if (ch + 1 < nchunks) {
            load_stage(stg ^ 1, ch + 1);
            CP_COMMIT();
            CP_WAIT(1);
        } else {
            CP_WAIT(0);
        }
        __syncthreads();

        const uint32_t sb = sm_base + (uint32_t)stg * (STAGE_E * 2);
        #pragma unroll
        for (int ks = 0; ks < 2; ks++) {
            const uint32_t kA = (uint32_t)(ks * 16) * 2;
            const uint32_t kB = (uint32_t)(ks * 16 * BLD) * 2;
            uint32_t aH[2][4], aL[2][4], bH[4][2], bL[4][2];
            #pragma unroll
            for (int mi = 0; mi < 2; mi++) {
                uint32_t off = (uint32_t)(mi * 16 * ALD) * 2 + kA;
                ldsm4(aH[mi][0], aH[mi][1], aH[mi][2], aH[mi][3], sb + aHoff + off);
                ldsm4(aL[mi][0], aL[mi][1], aL[mi][2], aL[mi][3], sb + aLoff + off);
            }
            // B: one x4.trans per ni-pair per plane (covers 16 cols)
            #pragma unroll
            for (int np = 0; np < 2; np++) {
                uint32_t off = kB + (uint32_t)(np * 16) * 2;
                ldsm4t(bH[np * 2][0], bH[np * 2][1], bH[np * 2 + 1][0], bH[np * 2 + 1][1],
                       sb + bHoff + off);
                ldsm4t(bL[np * 2][0], bL[np * 2][1], bL[np * 2 + 1][0], bL[np * 2 + 1][1],
                       sb + bLoff + off);
            }
            #pragma unroll
            for (int mi = 0; mi < 2; mi++)
                #pragma unroll
                for (int ni = 0; ni < 4; ni++) {
                    mma16816(acc[mi][ni], aH[mi], bH[ni]);
                    mma16816(acc[mi][ni], aH[mi], bL[ni]);
                    mma16816(acc[mi][ni], aL[mi], bH[ni]);
                }
        }
        __syncthreads();
    }

    const int cr = lane >> 2;
    const int cc = (lane & 3) * 2;
    #pragma unroll
    for (int mi = 0; mi < 2; mi++)
        #pragma unroll
        for (int ni = 0; ni < 4; ni++) {
            int row = m0 + mw + mi * 16 + cr;
            int col = n0 + nw + ni * 8 + cc;
            if (Cf) {
                *reinterpret_cast<float2*>(Cf + (size_t)row * ldc + col) =
                    make_float2(acc[mi][ni][0], acc[mi][ni][1]);
                *reinterpret_cast<float2*>(Cf + (size_t)(row + 8) * ldc + col) =
                    make_float2(acc[mi][ni][2], acc[mi][ni][3]);
            }
            if (Ch) {
                uint32_t h0, l0, h1, l1;
                split2(acc[mi][ni][0], acc[mi][ni][1], h0, l0);
                split2(acc[mi][ni][2], acc[mi][ni][3], h1, l1);
                *reinterpret_cast<uint32_t*>(Ch + (size_t)row * ldh + col)       = h0;
                *reinterpret_cast<uint32_t*>(Cl + (size_t)row * ldh + col)       = l0;
                *reinterpret_cast<uint32_t*>(Ch + (size_t)(row + 8) * ldh + col) = h1;
                *reinterpret_cast<uint32_t*>(Cl + (size_t)(row + 8) * ldh + col) = l1;
            }
        }
}

// ---------------- RoPE on hi/lo planes ----------------
__global__ void rope_kernel()
{
    const int row  = blockIdx.x;
    const int pos  = row & (SEQ - 1);
    const int warp = threadIdx.x >> 5;
    const int lane = threadIdx.x & 31;

    float theta = __powf(10000.0f, -(float)lane * (1.0f / 32.0f));
    float ang = (float)pos * theta;
    float s, c;
    sincosf(ang, &s, &c);

    if (warp < 16) {
        size_t off = (size_t)row * 3072 + warp * 192 + 128 + 2 * lane;
        uint32_t hv = *reinterpret_cast<uint32_t*>(g_qbh + off);
        uint32_t lv = *reinterpret_cast<uint32_t*>(g_qbl + off);
        __nv_bfloat162 h2 = *reinterpret_cast<__nv_bfloat162*>(&hv);
        __nv_bfloat162 l2 = *reinterpret_cast<__nv_bfloat162*>(&lv);
        float x1 = __bfloat162float(h2.x) + __bfloat162float(l2.x);
        float x2 = __bfloat162float(h2.y) + __bfloat162float(l2.y);
        float o1 = x1 * c - x2 * s;
        float o2 = x1 * s + x2 * c;
        uint32_t oh, ol;
        split2(o1, o2, oh, ol);
        *reinterpret_cast<uint32_t*>(g_qbh + off) = oh;
        *reinterpret_cast<uint32_t*>(g_qbl + off) = ol;
    } else {
        size_t off = (size_t)row * 576 + 512 + 2 * lane;
        uint32_t hv = *reinterpret_cast<uint32_t*>(g_ckvh + off);
        uint32_t lv = *reinterpret_cast<uint32_t*>(g_ckvl + off);
        __nv_bfloat162 h2 = *reinterpret_cast<__nv_bfloat162*>(&hv);
        __nv_bfloat162 l2 = *reinterpret_cast<__nv_bfloat162*>(&lv);
        float x1 = __bfloat162float(h2.x) + __bfloat162float(l2.x);
        float x2 = __bfloat162float(h2.y) + __bfloat162float(l2.y);
        float o1 = x1 * c - x2 * s;
        float o2 = x1 * s + x2 * c;
        uint32_t oh, ol;
        split2(o1, o2, oh, ol);
        size_t po = (size_t)row * 64 + 2 * lane;
        *reinterpret_cast<uint32_t*>(g_peh + po) = oh;
        *reinterpret_cast<uint32_t*>(g_pel + po) = ol;
    }
}

// ================= HMMA flash attention, bf16 3-pass split =================
#define QT 128
#define KT 32
#define QLD 200
#define KLD 200
#define VLD 136
#define AQ_H 0
#define AQ_L (QT * QLD)
#define AK   (2 * QT * QLD)
#define K_STG (2 * KT * KLD)
#define K_PL  (KT * KLD)
#define AV   (AK + 2 * K_STG)
#define V_STG (2 * KT * VLD)
#define V_PL  (KT * VLD)
#define ATT_E (AV + 2 * V_STG)
#define ATT_SMEM (ATT_E * 2)

__global__ __launch_bounds__(256, 1) void attn_hmma()
{
    extern __shared__ __nv_bfloat16 sm[];
    const int tid = threadIdx.x, wid = tid >> 5, lane = tid & 31;
    const int b = blockIdx.z, h = blockIdx.y;
    const int q0 = blockIdx.x * QT;
    const uint32_t sb = smem_u32(sm);
    const float scale = 0.07216878364870323f;   // 1/sqrt(192)

    {
        int r = tid >> 1;
        size_t row = (size_t)(b * SEQ + q0 + r) * 3072 + h * 192;
        const __nv_bfloat16* srch = g_qbh + row;
        const __nv_bfloat16* srcl = g_qbl + row;
        uint32_t dsth = sb + (uint32_t)(AQ_H + r * QLD) * 2;
        uint32_t dstl = sb + (uint32_t)(AQ_L + r * QLD) * 2;
        #pragma unroll
        for (int s = 0; s < 12; s++) {
            int seg = (tid & 1) * 12 + s;
            cp16(dsth + seg * 16, srch + seg * 8);
            cp16(dstl + seg * 16, srcl + seg * 8);
        }
    }

    auto load_kv = [&](int stg, int kt0) {
        int r = tid >> 3;
        size_t row = (size_t)(b * SEQ + kt0 + r);
        const __nv_bfloat16* knh = g_kvh + row * 4096 + h * 256;
        const __nv_bfloat16* knl = g_kvl + row * 4096 + h * 256;
        const __nv_bfloat16* peh = g_peh + row * 64;
        const __nv_bfloat16* pel = g_pel + row * 64;
        uint32_t kdh = sb + (uint32_t)(AK + stg * K_STG + r * KLD) * 2;
        uint32_t kdl = kdh + (uint32_t)K_PL * 2;
        uint32_t vdh = sb + (uint32_t)(AV + stg * V_STG + r * VLD) * 2;
        uint32_t vdl = vdh + (uint32_t)V_PL * 2;
        #pragma unroll
        for (int s = 0; s < 10; s++) {
            int seg = (tid & 7) * 10 + s;
            if (seg < 16)      cp16(kdh + seg * 16, knh + seg * 8);
            else if (seg < 24) cp16(kdh + seg * 16, peh + (seg - 16) * 8);
            else if (seg < 40) cp16(kdl + (seg - 24) * 16, knl + (seg - 24) * 8);
            else if (seg < 48) cp16(kdl + (seg - 24) * 16, pel + (seg - 40) * 8);
            else if (seg < 64) cp16(vdh + (seg - 48) * 16, knh + 128 + (seg - 48) * 8);
            else               cp16(vdl + (seg - 64) * 16, knl + 128 + (seg - 64) * 8);
        }
    };

    load_kv(0, 0);
    CP_COMMIT();

    const int ntiles = q0 / KT + QT / KT;
    float m0 = -INFINITY, m1 = -INFINITY, l0 = 0.f, l1 = 0.f;
    float O[16][4];
    #pragma unroll
    for (int od = 0; od < 16; od++)
        #pragma unroll
        for (int e = 0; e < 4; e++) O[od][e] = 0.f;

    const uint32_t qb_h = sb + (uint32_t)(AQ_H + (wid * 16 + (lane & 15)) * QLD + (lane >> 4) * 8) * 2;
    const uint32_t qb_l = qb_h + (uint32_t)(QT * QLD) * 2;

    for (int t = 0; t < ntiles; t++) {
        const int stg = t & 1;
        if (t + 1 < ntiles) {
            load_kv(stg ^ 1, (t + 1) * KT);
            CP_COMMIT();
            CP_WAIT(1);
        } else {
            CP_WAIT(0);
        }
        __syncthreads();

        float S[4][4];
        #pragma unroll
        for (int g = 0; g < 4; g++)
            #pragma unroll
            for (int e = 0; e < 4; e++) S[g][e] = 0.f;

        const uint32_t kb_h = sb + (uint32_t)(AK + stg * K_STG + (lane & 15) * KLD + (lane >> 4) * 8) * 2;
        const uint32_t kb_l = kb_h + (uint32_t)K_PL * 2;
        #pragma unroll
        for (int ks = 0; ks < 12; ks++) {
            uint32_t aH[4], aL[4];
            ldsm4(aH[0], aH[1], aH[2], aH[3], qb_h + ks * 32);
            ldsm4(aL[0], aL[1], aL[2], aL[3], qb_l + ks * 32);
            #pragma unroll
            for (int np = 0; np < 2; np++) {
                uint32_t off = (uint32_t)(np * 16 * KLD) * 2 + ks * 32;
                uint32_t h0, h1, h2, h3, l0r, l1r, l2r, l3r;
                ldsm4(h0, h1, h2, h3, kb_h + off);
                ldsm4(l0r, l1r, l2r, l3r, kb_l + off);
                uint32_t bh0[2] = {h0, h2},  bh1[2] = {h1, h3};
                uint32_t bl0[2] = {l0r, l2r}, bl1[2] = {l1r, l3r};
                mma16816(S[np * 2],     aH, bh0);
                mma16816(S[np * 2],     aH, bl0);
                mma16816(S[np * 2],     aL, bh0);
                mma16816(S[np * 2 + 1], aH, bh1);
                mma16816(S[np * 2 + 1], aH, bl1);
                mma16816(S[np * 2 + 1], aL, bh1);
            }
        }

        const int mrow0 = q0 + wid * 16 + (lane >> 2);
        const int kcol0 = t * KT + (lane & 3) * 2;
        const bool needmask = (t * KT + KT - 1) > (q0 + wid * 16);
        if (needmask) {
            #pragma unroll
            for (int g = 0; g < 4; g++) {
                int kc = kcol0 + g * 8;
                S[g][0] = (kc     <= mrow0)     ? S[g][0] * scale : -INFINITY;
                S[g][1] = (kc + 1 <= mrow0)     ? S[g][1] * scale : -INFINITY;
                S[g][2] = (kc     <= mrow0 + 8) ? S[g][2] * scale : -INFINITY;
                S[g][3] = (kc + 1 <= mrow0 + 8) ? S[g][3] * scale : -INFINITY;
            }
        } else {
            #pragma unroll
            for (int g = 0; g < 4; g++)
                #pragma unroll
                for (int e = 0; e < 4; e++) S[g][e] *= scale;
        }

        float tm0 = -INFINITY, tm1 = -INFINITY;
        #pragma unroll
        for (int g = 0; g < 4; g++) {
            tm0 = fmaxf(tm0, fmaxf(S[g][0], S[g][1]));
            tm1 = fmaxf(tm1, fmaxf(S[g][2], S[g][3]));
        }
        tm0 = fmaxf(tm0, __shfl_xor_sync(0xffffffffu, tm0, 1));
        tm0 = fmaxf(tm0, __shfl_xor_sync(0xffffffffu, tm0, 2));
        tm1 = fmaxf(tm1, __shfl_xor_sync(0xffffffffu, tm1, 1));
        tm1 = fmaxf(tm1, __shfl_xor_sync(0xffffffffu, tm1, 2));

        float mn0 = fmaxf(m0, tm0), mn1 = fmaxf(m1, tm1);
        float al0 = __expf(m0 - mn0), al1 = __expf(m1 - mn1);
        m0 = mn0; m1 = mn1;

        float P[4][4];
        float s0 = 0.f, s1 = 0.f;
        #pragma unroll
        for (int g = 0; g < 4; g++) {
            P[g][0] = __expf(S[g][0] - m0); s0 += P[g][0];
            P[g][1] = __expf(S[g][1] - m0); s0 += P[g][1];
            P[g][2] = __expf(S[g][2] - m1); s1 += P[g][2];
            P[g][3] = __expf(S[g][3] - m1); s1 += P[g][3];
        }
        s0 += __shfl_xor_sync(0xffffffffu, s0, 1);
        s0 += __shfl_xor_sync(0xffffffffu, s0, 2);
        s1 += __shfl_xor_sync(0xffffffffu, s1, 1);
        s1 += __shfl_xor_sync(0xffffffffu, s1, 2);
        l0 = l0 * al0 + s0;
        l1 = l1 * al1 + s1;

        #pragma unroll
        for (int od = 0; od < 16; od++) {
            O[od][0] *= al0; O[od][1] *= al0;
            O[od][2] *= al1; O[od][3] *= al1;
        }

        uint32_t aPh[2][4], aPl[2][4];
        #pragma unroll
        for (int kp = 0; kp < 2; kp++) {
            #pragma unroll
            for (int rr = 0; rr < 2; rr++) {
                #pragma unroll
                for (int hh = 0; hh < 2; hh++) {
                    float pa = P[2 * kp + hh][rr * 2 + 0];
                    float pb = P[2 * kp + hh][rr * 2 + 1];
                    split2(pa, pb, aPh[kp][hh * 2 + rr], aPl[kp][hh * 2 + rr]);
                }
            }
        }

        // V loads via x4.trans: lanes 16-31 cover cols +8, one instr = 2 od-frags
        const uint32_t vb_h = sb + (uint32_t)(AV + stg * V_STG + (lane & 15) * VLD + (lane >> 4) * 8) * 2;
        const uint32_t vb_l = vb_h + (uint32_t)V_PL * 2;
        #pragma unroll
        for (int kp = 0; kp < 2; kp++) {
            const uint32_t vkh = vb_h + (uint32_t)(kp * 16 * VLD) * 2;
            const uint32_t vkl = vb_l + (uint32_t)(kp * 16 * VLD) * 2;
            #pragma unroll
            for (int od2 = 0; od2 < 8; od2++) {
                uint32_t bh[4], bl[4];
                ldsm4t(bh[0], bh[1], bh[2], bh[3], vkh + od2 * 32);
                ldsm4t(bl[0], bl[1], bl[2], bl[3], vkl + od2 * 32);
                mma16816(O[od2 * 2],     aPh[kp], bh);
                mma16816(O[od2 * 2],     aPh[kp], bl);
                mma16816(O[od2 * 2],     aPl[kp], bh);
                mma16816(O[od2 * 2 + 1], aPh[kp], bh + 2);
                mma16816(O[od2 * 2 + 1], aPh[kp], bl + 2);
                mma16816(O[od2 * 2 + 1], aPl[kp], bh + 2);
            }
        }
        __syncthreads();
    }

    // ---- normalize + split write to ah/al planes ----
    float inv0 = 1.f / l0, inv1 = 1.f / l1;
    int row0 = b * SEQ + q0 + wid * 16 + (lane >> 2);
    size_t o0 = (size_t)row0 * 2048 + h * 128 + (lane & 3) * 2;
    size_t o1 = (size_t)(row0 + 8) * 2048 + h * 128 + (lane & 3) * 2;
    #pragma unroll
    for (int od = 0; od < 16; od++) {
        uint32_t h0, l0p, h1, l1p;
        split2(O[od][0] * inv0, O[od][1] * inv0, h0, l0p);
        split2(O[od][2] * inv1, O[od][3] * inv1, h1, l1p);
        *reinterpret_cast<uint32_t*>(g_ah + o0 + od * 8) = h0;
        *reinterpret_cast<uint32_t*>(g_al + o0 + od * 8) = l0p;
        *reinterpret_cast<uint32_t*>(g_ah + o1 + od * 8) = h1;
        *reinterpret_cast<uint32_t*>(g_al + o1 + od * 8) = l1p;
    }
}

// ---------------- launch ----------------
static inline void conv(const float* in, __nv_bfloat16* hi, __nv_bfloat16* lo, int nelem)
{
    int n4 = nelem / 4;
    conv_split<<<(n4 + 255) / 256, 256>>>(in, hi, lo, n4);
}

extern "C" void kernel_launch(void* const* d_in, const int* in_sizes, int n_in,
                              void* d_out, int out_size)
{
    const float* x    = (const float*)d_in[0];
    const float* Wqa  = (const float*)d_in[1];
    const float* Wqb  = (const float*)d_in[2];
    const float* Wkva = (const float*)d_in[3];
    const float* Wkvb = (const float*)d_in[4];
    const float* Wout = (const float*)d_in[5];
    float* out = (float*)d_out;

    __nv_bfloat16 *xh, *xl, *q1h, *q1l, *ckvh, *ckvl, *qbh, *qbl, *kvh, *kvl, *ah, *al;
    __nv_bfloat16 *wqah, *wqal, *wqbh, *wqbl, *wkvah, *wkval, *wkvbh, *wkvbl, *wouth, *woutl;
    cudaGetSymbolAddress((void**)&xh,   g_xh);   cudaGetSymbolAddress((void**)&xl,   g_xl);
    cudaGetSymbolAddress((void**)&q1h,  g_q1h);  cudaGetSymbolAddress((void**)&q1l,  g_q1l);
    cudaGetSymbolAddress((void**)&ckvh, g_ckvh); cudaGetSymbolAddress((void**)&ckvl, g_ckvl);
    cudaGetSymbolAddress((void**)&qbh,  g_qbh);  cudaGetSymbolAddress((void**)&qbl,  g_qbl);
    cudaGetSymbolAddress((void**)&kvh,  g_kvh);  cudaGetSymbolAddress((void**)&kvl,  g_kvl);
    cudaGetSymbolAddress((void**)&ah,   g_ah);   cudaGetSymbolAddress((void**)&al,   g_al);
    cudaGetSymbolAddress((void**)&wqah, g_Wqah); cudaGetSymbolAddress((void**)&wqal, g_Wqal);
    cudaGetSymbolAddress((void**)&wqbh, g_Wqbh); cudaGetSymbolAddress((void**)&wqbl, g_Wqbl);
    cudaGetSymbolAddress((void**)&wkvah, g_Wkvah); cudaGetSymbolAddress((void**)&wkval, g_Wkval);
    cudaGetSymbolAddress((void**)&wkvbh, g_Wkvbh); cudaGetSymbolAddress((void**)&wkvbl, g_Wkvbl);
    cudaGetSymbolAddress((void**)&wouth, g_Wouth); cudaGetSymbolAddress((void**)&woutl, g_Woutl);

    cudaFuncSetAttribute(gemm_hmma,
                         cudaFuncAttributeMaxDynamicSharedMemorySize, GEMM_SMEM);
    cudaFuncSetAttribute(attn_hmma,
                         cudaFuncAttributeMaxDynamicSharedMemorySize, ATT_SMEM);

    // ---- input conversions ----
    conv(x,    xh,    xl,    NROWS * 2048);
    conv(Wqa,  wqah,  wqal,  2048 * 512);
    conv(Wqb,  wqbh,  wqbl,  512 * 3072);
    conv(Wkva, wkvah, wkval, 2048 * 576);
    conv(Wkvb, wkvbh, wkvbl, 512 * 4096);
    conv(Wout, wouth, woutl, 2048 * 2048);

    dim3 t(256);
    // q1 = x @ Wqa -> hi/lo planes
    gemm_hmma<<<dim3(8, 32),  t, GEMM_SMEM>>>(xh, xl, 2048, wqah, wqal, 512,
                                              nullptr, 0, q1h, q1l, 512, 64);
    // q = q1 @ Wqb -> hi/lo planes
    gemm_hmma<<<dim3(48, 32), t, GEMM_SMEM>>>(q1h, q1l, 512, wqbh, wqbl, 3072,
                                              nullptr, 0, qbh, qbl, 3072, 16);
    // ckv = x @ Wkva -> hi/lo planes
    gemm_hmma<<<dim3(9, 32),  t, GEMM_SMEM>>>(xh, xl, 2048, wkvah, wkval, 576,
                                              nullptr, 0, ckvh, ckvl, 576, 64);
    // rope (q_pe in place; k_pe -> pe planes)
    rope_kernel<<<4096, 544>>>();
    // kv = ckv[:, :512] @ Wkvb -> hi/lo planes
    gemm_hmma<<<dim3(64, 32), t, GEMM_SMEM>>>(ckvh, ckvl, 576, wkvbh, wkvbl, 4096,
                                              nullptr, 0, kvh, kvl, 4096, 16);
    // flash attention -> ah/al planes
    attn_hmma<<<dim3(SEQ / QT, NHEADS, 2), 256, ATT_SMEM>>>();
    // out = att @ Wout -> fp32 output
    gemm_hmma<<<dim3(32, 32), t, GEMM_SMEM>>>(ah, al, 2048, wouth, woutl, 2048,
                                              out, 2048, nullptr, nullptr, 0, 64);
}

// round 12
// speedup vs baseline: 15.8880x; 2.3764x over previous
#include <cuda_runtime.h>
#include <cuda_fp16.h>
#include <math.h>
#include <stdint.h>

#define SEQ    2048
#define NROWS  4096
#define NHEADS 16

// ---------------- fp16 planes ----------------
__device__ __half g_xh [NROWS * 2048];
__device__ __half g_q1h[NROWS * 512];
__device__ __half g_ckvh[NROWS * 576];
__device__ __half g_qh [NROWS * 3072];
__device__ __half g_kvh[NROWS * 4096];
__device__ __half g_peh[NROWS * 64];
__device__ __half g_ah [NROWS * 2048];
__device__ __half g_Wqah[2048 * 512];
__device__ __half g_Wqbh[512 * 3072];
__device__ __half g_Wkvah[2048 * 576];
__device__ __half g_Wkvbh[512 * 4096];
__device__ __half g_Wouth[2048 * 2048];

// ================= helpers =================
__device__ __forceinline__ uint32_t smem_u32(const void* p) {
    uint32_t a;
    asm("{ .reg .u64 t; cvta.to.shared.u64 t, %1; cvt.u32.u64 %0, t; }" : "=r"(a) : "l"(p));
    return a;
}
__device__ __forceinline__ void ldsm4(uint32_t& r0, uint32_t& r1, uint32_t& r2, uint32_t& r3,
                                      uint32_t addr) {
    asm volatile("ldmatrix.sync.aligned.m8n8.x4.shared.b16 {%0,%1,%2,%3}, [%4];"
                 : "=r"(r0), "=r"(r1), "=r"(r2), "=r"(r3) : "r"(addr));
}
__device__ __forceinline__ void ldsm4t(uint32_t& r0, uint32_t& r1, uint32_t& r2, uint32_t& r3,
                                       uint32_t addr) {
    asm volatile("ldmatrix.sync.aligned.m8n8.x4.trans.shared.b16 {%0,%1,%2,%3}, [%4];"
                 : "=r"(r0), "=r"(r1), "=r"(r2), "=r"(r3) : "r"(addr));
}
__device__ __forceinline__ void mma16816(float* c, const uint32_t* a, const uint32_t* b) {
    asm volatile(
        "mma.sync.aligned.m16n8k16.row.col.f32.f16.f16.f32 "
        "{%0,%1,%2,%3}, {%4,%5,%6,%7}, {%8,%9}, {%0,%1,%2,%3};"
        : "+f"(c[0]), "+f"(c[1]), "+f"(c[2]), "+f"(c[3])
        : "r"(a[0]), "r"(a[1]), "r"(a[2]), "r"(a[3]), "r"(b[0]), "r"(b[1]));
}
__device__ __forceinline__ void cp16(uint32_t saddr, const void* g) {
    asm volatile("cp.async.ca.shared.global [%0], [%1], 16;" :: "r"(saddr), "l"(g));
}
#define CP_COMMIT() asm volatile("cp.async.commit_group;" ::: "memory")
#define CP_WAIT(n)  asm volatile("cp.async.wait_group %0;" :: "n"(n) : "memory")

__device__ __forceinline__ uint32_t pack_h2(float a, float b) {
    __half2 t = __floats2half2_rn(a, b);
    return *reinterpret_cast<uint32_t*>(&t);
}

// ---------------- input conversion (fp32 -> fp16) ----------------
__global__ void conv_h(const float* __restrict__ in, __half* __restrict__ out, int n4)
{
    int i = blockIdx.x * blockDim.x + threadIdx.x;
    if (i < n4) {
        float4 v = reinterpret_cast<const float4*>(in)[i];
        uint2 o;
        o.x = pack_h2(v.x, v.y);
        o.y = pack_h2(v.z, v.w);
        reinterpret_cast<uint2*>(out)[i] = o;
    }
}

// ================= HMMA fp16 GEMM =================
// C[M,N] = A[M,K] @ B[K,N]. CTA 128x64, K-chunk 32, 256 thr, 8 warps (32x32 each).
#define KCH 32
#define ALD 40
#define BLD 72
#define A_PLANE (128 * ALD)
#define B_PLANE (KCH * BLD)
#define OFF_A 0
#define OFF_B A_PLANE
#define STAGE_E (A_PLANE + B_PLANE)          // 7424 elems
#define GEMM_SMEM (2 * STAGE_E * 2)          // 29696 bytes

__global__ __launch_bounds__(256) void gemm_hmma(
    const __half* __restrict__ A, int lda,
    const __half* __restrict__ B, int ldb,
    float* __restrict__ Cf, int ldc,
    __half* __restrict__ Ch, int ldh,
    int nchunks)
{
    extern __shared__ __half sm[];
    const int tid  = threadIdx.x;
    const int wid  = tid >> 5;
    const int lane = tid & 31;
    const int m0 = blockIdx.y * 128;
    const int n0 = blockIdx.x * 64;
    const int mw = (wid & 3) * 32;
    const int nw = (wid >> 2) * 32;
    const uint32_t sm_base = smem_u32(sm);

    float acc[2][4][4];
    #pragma unroll
    for (int i = 0; i < 2; i++)
        #pragma unroll
        for (int j = 0; j < 4; j++)
            #pragma unroll
            for (int e = 0; e < 4; e++) acc[i][j][e] = 0.f;

    const int ar  = tid >> 1;                // A: 128 rows x 2 threads (2 segs each)
    const int as  = (tid & 1) * 2;
    const int br  = tid >> 3;                // B: 32 rows x 8 segs
    const int bs  = tid & 7;

    const uint32_t aRow = lane & 15;
    const uint32_t aCol = (lane >> 4) * 8;
    const uint32_t aOff = (uint32_t)(OFF_A + (mw + aRow) * ALD + aCol) * 2;
    const uint32_t bOff = (uint32_t)(OFF_B + (lane & 15) * BLD + nw + (lane >> 4) * 8) * 2;

    auto load_stage = [&](int stg, int ch) {
        const uint32_t sb = sm_base + (uint32_t)stg * (STAGE_E * 2);
        const int k0 = ch * KCH;
        #pragma unroll
        for (int s = 0; s < 2; s++) {
            int seg = as + s;
            cp16(sb + (uint32_t)(OFF_A + ar * ALD + seg * 8) * 2,
                 A + (size_t)(m0 + ar) * lda + k0 + seg * 8);
        }
        cp16(sb + (uint32_t)(OFF_B + br * BLD + bs * 8) * 2,
             B + (size_t)(k0 + br) * ldb + n0 + bs * 8);
    };

    load_stage(0, 0);
    CP_COMMIT();

    for (int ch = 0; ch < nchunks; ch++) {
        const int stg = ch & 1;
        if (ch + 1 < nchunks) {
            load_stage(stg ^ 1, ch + 1);
            CP_COMMIT();
            CP_WAIT(1);
        } else {
            CP_WAIT(0);
        }
        __syncthreads();

        const uint32_t sb = sm_base + (uint32_t)stg * (STAGE_E * 2);
        #pragma unroll
        for (int ks = 0; ks < 2; ks++) {
            const uint32_t kA = (uint32_t)(ks * 16) * 2;
            const uint32_t kB = (uint32_t)(ks * 16 * BLD) * 2;
            uint32_t a[2][4], b[4][2];
            #pragma unroll
            for (int mi = 0; mi < 2; mi++) {
                uint32_t off = (uint32_t)(mi * 16 * ALD) * 2 + kA;
                ldsm4(a[mi][0], a[mi][1], a[mi][2], a[mi][3], sb + aOff + off);
            }
            #pragma unroll
            for (int np = 0; np < 2; np++) {
                uint32_t off = kB + (uint32_t)(np * 16) * 2;
                ldsm4t(b[np * 2][0], b[np * 2][1], b[np * 2 + 1][0], b[np * 2 + 1][1],
                       sb + bOff + off);
            }
            #pragma unroll
            for (int mi = 0; mi < 2; mi++)
                #pragma unroll
                for (int ni = 0; ni < 4; ni++)
                    mma16816(acc[mi][ni], a[mi], b[ni]);
        }
        __syncthreads();
    }

    const int cr = lane >> 2;
    const int cc = (lane & 3) * 2;
    #pragma unroll
    for (int mi = 0; mi < 2; mi++)
        #pragma unroll
        for (int ni = 0; ni < 4; ni++) {
            int row = m0 + mw + mi * 16 + cr;
            int col = n0 + nw + ni * 8 + cc;
            if (Cf) {
                *reinterpret_cast<float2*>(Cf + (size_t)row * ldc + col) =
                    make_float2(acc[mi][ni][0], acc[mi][ni][1]);
                *reinterpret_cast<float2*>(Cf + (size_t)(row + 8) * ldc + col) =
                    make_float2(acc[mi][ni][2], acc[mi][ni][3]);
            }
            if (Ch) {
                *reinterpret_cast<uint32_t*>(Ch + (size_t)row * ldh + col) =
                    pack_h2(acc[mi][ni][0], acc[mi][ni][1]);
                *reinterpret_cast<uint32_t*>(Ch + (size_t)(row + 8) * ldh + col) =
                    pack_h2(acc[mi][ni][2], acc[mi][ni][3]);
            }
        }
}

// ---------------- RoPE on fp16 planes ----------------
__global__ void rope_kernel()
{
    const int row  = blockIdx.x;
    const int pos  = row & (SEQ - 1);
    const int warp = threadIdx.x >> 5;
    const int lane = threadIdx.x & 31;

    float theta = __powf(10000.0f, -(float)lane * (1.0f / 32.0f));
    float ang = (float)pos * theta;
    float s, c;
    sincosf(ang, &s, &c);

    if (warp < 16) {
        size_t off = (size_t)row * 3072 + warp * 192 + 128 + 2 * lane;
        uint32_t hv = *reinterpret_cast<uint32_t*>(g_qh + off);
        __half2 h2 = *reinterpret_cast<__half2*>(&hv);
        float x1 = __half2float(h2.x);
        float x2 = __half2float(h2.y);
        *reinterpret_cast<uint32_t*>(g_qh + off) =
            pack_h2(x1 * c - x2 * s, x1 * s + x2 * c);
    } else {
        size_t off = (size_t)row * 576 + 512 + 2 * lane;
        uint32_t hv = *reinterpret_cast<uint32_t*>(g_ckvh + off);
        __half2 h2 = *reinterpret_cast<__half2*>(&hv);
        float x1 = __half2float(h2.x);
        float x2 = __half2float(h2.y);
        *reinterpret_cast<uint32_t*>(g_peh + (size_t)row * 64 + 2 * lane) =
            pack_h2(x1 * c - x2 * s, x1 * s + x2 * c);
    }
}

// ================= HMMA fp16 flash attention =================
// Block 256 thr (8 warps, 16 q-rows each), q-tile 128, key tiles 32 double-buffered.
#define QT 128
#define KT 32
#define QLD 200
#define KLD 200
#define VLD 136
#define AQ 0
#define AK (QT * QLD)                        // 25600
#define K_STG (KT * KLD)                     // 6400
#define AV (AK + 2 * K_STG)                  // 38400
#define V_STG (KT * VLD)                     // 4352
#define ATT_E (AV + 2 * V_STG)               // 47104 elems
#define ATT_SMEM (ATT_E * 2)                 // 94208 bytes

__global__ __launch_bounds__(256, 1) void attn_hmma()
{
    extern __shared__ __half sm[];
    const int tid = threadIdx.x, wid = tid >> 5, lane = tid & 31;
    const int b = blockIdx.z, h = blockIdx.y;
    const int q0 = blockIdx.x * QT;
    const uint32_t sb = smem_u32(sm);
    const float scale = 0.07216878364870323f;   // 1/sqrt(192)

    // ---- async load Q tile [128][192] ----
    {
        int r = tid >> 1;
        const __half* src = g_qh + (size_t)(b * SEQ + q0 + r) * 3072 + h * 192;
        uint32_t dst = sb + (uint32_t)(AQ + r * QLD) * 2;
        #pragma unroll
        for (int s = 0; s < 12; s++) {
            int seg = (tid & 1) * 12 + s;
            cp16(dst + seg * 16, src + seg * 8);
        }
    }

    auto load_kv = [&](int stg, int kt0) {
        int r = tid >> 3;                     // 32 rows x 8 threads
        size_t row = (size_t)(b * SEQ + kt0 + r);
        const __half* kn = g_kvh + row * 4096 + h * 256;
        const __half* pe = g_peh + row * 64;
        uint32_t kd = sb + (uint32_t)(AK + stg * K_STG + r * KLD) * 2;
        uint32_t vd = sb + (uint32_t)(AV + stg * V_STG + r * VLD) * 2;
        #pragma unroll
        for (int s = 0; s < 5; s++) {
            int seg = (tid & 7) * 5 + s;
            if (seg < 16)      cp16(kd + seg * 16, kn + seg * 8);
            else if (seg < 24) cp16(kd + seg * 16, pe + (seg - 16) * 8);
            else               cp16(vd + (seg - 24) * 16, kn + 128 + (seg - 24) * 8);
        }
    };

    load_kv(0, 0);
    CP_COMMIT();

    const int ntiles = q0 / KT + QT / KT;
    float m0 = -INFINITY, m1 = -INFINITY, l0 = 0.f, l1 = 0.f;
    float O[16][4];
    #pragma unroll
    for (int od = 0; od < 16; od++)
        #pragma unroll
        for (int e = 0; e < 4; e++) O[od][e] = 0.f;

    const uint32_t qb = sb + (uint32_t)(AQ + (wid * 16 + (lane & 15)) * QLD + (lane >> 4) * 8) * 2;

    for (int t = 0; t < ntiles; t++) {
        const int stg = t & 1;
        if (t + 1 < ntiles) {
            load_kv(stg ^ 1, (t + 1) * KT);
            CP_COMMIT();
            CP_WAIT(1);
        } else {
            CP_WAIT(0);
        }
        __syncthreads();

        // ---- S = Q K^T ----
        float S[4][4];
        #pragma unroll
        for (int g = 0; g < 4; g++)
            #pragma unroll
            for (int e = 0; e < 4; e++) S[g][e] = 0.f;

        const uint32_t kb = sb + (uint32_t)(AK + stg * K_STG + (lane & 15) * KLD + (lane >> 4) * 8) * 2;
        #pragma unroll
        for (int ks = 0; ks < 12; ks++) {
            uint32_t a[4];
            ldsm4(a[0], a[1], a[2], a[3], qb + ks * 32);
            #pragma unroll
            for (int np = 0; np < 2; np++) {
                uint32_t off = (uint32_t)(np * 16 * KLD) * 2 + ks * 32;
                uint32_t h0, h1, h2, h3;
                ldsm4(h0, h1, h2, h3, kb + off);
                uint32_t b0[2] = {h0, h2}, b1[2] = {h1, h3};
                mma16816(S[np * 2],     a, b0);
                mma16816(S[np * 2 + 1], a, b1);
            }
        }

        // ---- scale + causal mask ----
        const int mrow0 = q0 + wid * 16 + (lane >> 2);
        const int kcol0 = t * KT + (lane & 3) * 2;
        const bool needmask = (t * KT + KT - 1) > (q0 + wid * 16);
        if (needmask) {
            #pragma unroll
            for (int g = 0; g < 4; g++) {
                int kc = kcol0 + g * 8;
                S[g][0] = (kc     <= mrow0)     ? S[g][0] * scale : -INFINITY;
                S[g][1] = (kc + 1 <= mrow0)     ? S[g][1] * scale : -INFINITY;
                S[g][2] = (kc     <= mrow0 + 8) ? S[g][2] * scale : -INFINITY;
                S[g][3] = (kc + 1 <= mrow0 + 8) ? S[g][3] * scale : -INFINITY;
            }
        } else {
            #pragma unroll
            for (int g = 0; g < 4; g++)
                #pragma unroll
                for (int e = 0; e < 4; e++) S[g][e] *= scale;
        }

        // ---- online softmax ----
        float tm0 = -INFINITY, tm1 = -INFINITY;
        #pragma unroll
        for (int g = 0; g < 4; g++) {
            tm0 = fmaxf(tm0, fmaxf(S[g][0], S[g][1]));
            tm1 = fmaxf(tm1, fmaxf(S[g][2], S[g][3]));
        }
        tm0 = fmaxf(tm0, __shfl_xor_sync(0xffffffffu, tm0, 1));
        tm0 = fmaxf(tm0, __shfl_xor_sync(0xffffffffu, tm0, 2));
        tm1 = fmaxf(tm1, __shfl_xor_sync(0xffffffffu, tm1, 1));
        tm1 = fmaxf(tm1, __shfl_xor_sync(0xffffffffu, tm1, 2));

        float mn0 = fmaxf(m0, tm0), mn1 = fmaxf(m1, tm1);
        float al0 = __expf(m0 - mn0), al1 = __expf(m1 - mn1);
        m0 = mn0; m1 = mn1;

        float P[4][4];
        float s0 = 0.f, s1 = 0.f;
        #pragma unroll
        for (int g = 0; g < 4; g++) {
            P[g][0] = __expf(S[g][0] - m0); s0 += P[g][0];
            P[g][1] = __expf(S[g][1] - m0); s0 += P[g][1];
            P[g][2] = __expf(S[g][2] - m1); s1 += P[g][2];
            P[g][3] = __expf(S[g][3] - m1); s1 += P[g][3];
        }
        s0 += __shfl_xor_sync(0xffffffffu, s0, 1);
        s0 += __shfl_xor_sync(0xffffffffu, s0, 2);
        s1 += __shfl_xor_sync(0xffffffffu, s1, 1);
        s1 += __shfl_xor_sync(0xffffffffu, s1, 2);
        l0 = l0 * al0 + s0;
        l1 = l1 * al1 + s1;

        #pragma unroll
        for (int od = 0; od < 16; od++) {
            O[od][0] *= al0; O[od][1] *= al0;
            O[od][2] *= al1; O[od][3] *= al1;
        }

        // ---- P -> fp16 a-frags ----
        uint32_t aP[2][4];
        #pragma unroll
        for (int kp = 0; kp < 2; kp++) {
            #pragma unroll
            for (int rr = 0; rr < 2; rr++) {
                #pragma unroll
                for (int hh = 0; hh < 2; hh++) {
                    aP[kp][hh * 2 + rr] = pack_h2(P[2 * kp + hh][rr * 2 + 0],
                                                  P[2 * kp + hh][rr * 2 + 1]);
                }
            }
        }

        // ---- O += P V ----
        const uint32_t vb = sb + (uint32_t)(AV + stg * V_STG + (lane & 15) * VLD + (lane >> 4) * 8) * 2;
        #pragma unroll
        for (int kp = 0; kp < 2; kp++) {
            const uint32_t vk = vb + (uint32_t)(kp * 16 * VLD) * 2;
            #pragma unroll
            for (int od2 = 0; od2 < 8; od2++) {
                uint32_t bv[4];
                ldsm4t(bv[0], bv[1], bv[2], bv[3], vk + od2 * 32);
                mma16816(O[od2 * 2],     aP[kp], bv);
                mma16816(O[od2 * 2 + 1], aP[kp], bv + 2);
            }
        }
        __syncthreads();
    }

    // ---- normalize + fp16 write ----
    float inv0 = 1.f / l0, inv1 = 1.f / l1;
    int row0 = b * SEQ + q0 + wid * 16 + (lane >> 2);
    size_t o0 = (size_t)row0 * 2048 + h * 128 + (lane & 3) * 2;
    size_t o1 = (size_t)(row0 + 8) * 2048 + h * 128 + (lane & 3) * 2;
    #pragma unroll
    for (int od = 0; od < 16; od++) {
        *reinterpret_cast<uint32_t*>(g_ah + o0 + od * 8) =
            pack_h2(O[od][0] * inv0, O[od][1] * inv0);
        *reinterpret_cast<uint32_t*>(g_ah + o1 + od * 8) =
            pack_h2(O[od][2] * inv1, O[od][3] * inv1);
    }
}

// ---------------- launch ----------------
static inline void conv(const float* in, __half* out, int nelem)
{
    int n4 = nelem / 4;
    conv_h<<<(n4 + 255) / 256, 256>>>(in, out, n4);
}

extern "C" void kernel_launch(void* const* d_in, const int* in_sizes, int n_in,
                              void* d_out, int out_size)
{
    const float* x    = (const float*)d_in[0];
    const float* Wqa  = (const float*)d_in[1];
    const float* Wqb  = (const float*)d_in[2];
    const float* Wkva = (const float*)d_in[3];
    const float* Wkvb = (const float*)d_in[4];
    const float* Wout = (const float*)d_in[5];
    float* out = (float*)d_out;

    __half *xh, *q1h, *ckvh, *qh, *kvh, *ah;
    __half *wqah, *wqbh, *wkvah, *wkvbh, *wouth;
    cudaGetSymbolAddress((void**)&xh,   g_xh);
    cudaGetSymbolAddress((void**)&q1h,  g_q1h);
    cudaGetSymbolAddress((void**)&ckvh, g_ckvh);
    cudaGetSymbolAddress((void**)&qh,   g_qh);
    cudaGetSymbolAddress((void**)&kvh,  g_kvh);
    cudaGetSymbolAddress((void**)&ah,   g_ah);
    cudaGetSymbolAddress((void**)&wqah, g_Wqah);
    cudaGetSymbolAddress((void**)&wqbh, g_Wqbh);
    cudaGetSymbolAddress((void**)&wkvah, g_Wkvah);
    cudaGetSymbolAddress((void**)&wkvbh, g_Wkvbh);
    cudaGetSymbolAddress((void**)&wouth, g_Wouth);

    cudaFuncSetAttribute(gemm_hmma,
                         cudaFuncAttributeMaxDynamicSharedMemorySize, GEMM_SMEM);
    cudaFuncSetAttribute(attn_hmma,
                         cudaFuncAttributeMaxDynamicSharedMemorySize, ATT_SMEM);

    // ---- input conversions ----
    conv(x,    xh,    NROWS * 2048);
    conv(Wqa,  wqah,  2048 * 512);
    conv(Wqb,  wqbh,  512 * 3072);
    conv(Wkva, wkvah, 2048 * 576);
    conv(Wkvb, wkvbh, 512 * 4096);
    conv(Wout, wouth, 2048 * 2048);

    dim3 t(256);
    // q1 = x @ Wqa -> fp16
    gemm_hmma<<<dim3(8, 32),  t, GEMM_SMEM>>>(xh, 2048, wqah, 512,
                                              nullptr, 0, q1h, 512, 64);
    // q = q1 @ Wqb -> fp16
    gemm_hmma<<<dim3(48, 32), t, GEMM_SMEM>>>(q1h, 512, wqbh, 3072,
                                              nullptr, 0, qh, 3072, 16);
    // ckv = x @ Wkva -> fp16
    gemm_hmma<<<dim3(9, 32),  t, GEMM_SMEM>>>(xh, 2048, wkvah, 576,
                                              nullptr, 0, ckvh, 576, 64);
    // rope (q_pe in place; k_pe -> pe plane)
    rope_kernel<<<4096, 544>>>();
    // kv = ckv[:, :512] @ Wkvb -> fp16
    gemm_hmma<<<dim3(64, 32), t, GEMM_SMEM>>>(ckvh, 576, wkvbh, 4096,
                                              nullptr, 0, kvh, 4096, 16);
    // flash attention -> fp16
    attn_hmma<<<dim3(SEQ / QT, NHEADS, 2), 256, ATT_SMEM>>>();
    // out = att @ Wout -> fp32
    gemm_hmma<<<dim3(32, 32), t, GEMM_SMEM>>>(ah, 2048, wouth, 2048,
                                              out, 2048, nullptr, 0, 64);
}

// round 14
// speedup vs baseline: 16.6136x; 1.0457x over previous
#include <cuda_runtime.h>
#include <cuda_fp16.h>
#include <math.h>
#include <stdint.h>

#define SEQ    2048
#define NROWS  4096
#define NHEADS 16

// ---------------- fp16 planes ----------------
__device__ __half g_xh [NROWS * 2048];
__device__ __half g_q1h[NROWS * 512];
__device__ __half g_ckvh[NROWS * 576];
__device__ __half g_qh [NROWS * 3072];
__device__ __half g_kvh[NROWS * 4096];
__device__ __half g_peh[NROWS * 64];
__device__ __half g_ah [NROWS * 2048];
__device__ __half g_Wqah[2048 * 512];
__device__ __half g_Wqbh[512 * 3072];
__device__ __half g_Wkvah[2048 * 576];
__device__ __half g_Wkvbh[512 * 4096];
__device__ __half g_Wouth[2048 * 2048];

// ================= helpers =================
__device__ __forceinline__ uint32_t smem_u32(const void* p) {
    uint32_t a;
    asm("{ .reg .u64 t; cvta.to.shared.u64 t, %1; cvt.u32.u64 %0, t; }" : "=r"(a) : "l"(p));
    return a;
}
__device__ __forceinline__ void ldsm4(uint32_t& r0, uint32_t& r1, uint32_t& r2, uint32_t& r3,
                                      uint32_t addr) {
    asm volatile("ldmatrix.sync.aligned.m8n8.x4.shared.b16 {%0,%1,%2,%3}, [%4];"
                 : "=r"(r0), "=r"(r1), "=r"(r2), "=r"(r3) : "r"(addr));
}
__device__ __forceinline__ void ldsm4t(uint32_t& r0, uint32_t& r1, uint32_t& r2, uint32_t& r3,
                                       uint32_t addr) {
    asm volatile("ldmatrix.sync.aligned.m8n8.x4.trans.shared.b16 {%0,%1,%2,%3}, [%4];"
                 : "=r"(r0), "=r"(r1), "=r"(r2), "=r"(r3) : "r"(addr));
}
__device__ __forceinline__ void mma16816(float* c, const uint32_t* a, const uint32_t* b) {
    asm volatile(
        "mma.sync.aligned.m16n8k16.row.col.f32.f16.f16.f32 "
        "{%0,%1,%2,%3}, {%4,%5,%6,%7}, {%8,%9}, {%0,%1,%2,%3};"
        : "+f"(c[0]), "+f"(c[1]), "+f"(c[2]), "+f"(c[3])
        : "r"(a[0]), "r"(a[1]), "r"(a[2]), "r"(a[3]), "r"(b[0]), "r"(b[1]));
}
__device__ __forceinline__ void cp16(uint32_t saddr, const void* g) {
    asm volatile("cp.async.ca.shared.global [%0], [%1], 16;" :: "r"(saddr), "l"(g));
}
#define CP_COMMIT() asm volatile("cp.async.commit_group;" ::: "memory")
#define CP_WAIT(n)  asm volatile("cp.async.wait_group %0;" :: "n"(n) : "memory")

__device__ __forceinline__ uint32_t pack_h2(float a, float b) {
    __half2 t = __floats2half2_rn(a, b);
    return *reinterpret_cast<uint32_t*>(&t);
}

// ---------------- input conversion ----------------
__global__ void conv_h(const float* __restrict__ in, __half* __restrict__ out, int n4)
{
    int i = blockIdx.x * blockDim.x + threadIdx.x;
    if (i < n4) {
        float4 v = reinterpret_cast<const float4*>(in)[i];
        uint2 o;
        o.x = pack_h2(v.x, v.y);
        o.y = pack_h2(v.z, v.w);
        reinterpret_cast<uint2*>(out)[i] = o;
    }
}

// ================= HMMA fp16 GEMM, templated N-tile =================
// C[M, n0..n0+NTILE) = A[M,K] @ B[K, n0..]. CTA 128 x NTILE, K-chunk 32, 256 thr.
#define KCH 32
#define ALD 40
#define A_PLANE (128 * ALD)

template<int NTILE>
__global__ __launch_bounds__(256) void gemm_hmma(
    const __half* __restrict__ A, int lda,
    const __half* __restrict__ B, int ldb,
    float* __restrict__ Cf, int ldc,
    __half* __restrict__ Ch, int ldh,
    int nchunks)
{
    constexpr int BLD = NTILE + 8;
    constexpr int B_PLANE = KCH * BLD;
    constexpr int STAGE_E = A_PLANE + B_PLANE;
    constexpr int NI = NTILE / 16;            // n-frags per warp
    constexpr int BSEG = NTILE / 64;          // B cp16 per thread

    extern __shared__ __half sm[];
    const int tid  = threadIdx.x;
    const int wid  = tid >> 5;
    const int lane = tid & 31;
    const int m0 = blockIdx.y * 128;
    const int n0 = blockIdx.x * NTILE;
    const int mw = (wid & 3) * 32;
    const int nw = (wid >> 2) * (NTILE / 2);
    const uint32_t sm_base = smem_u32(sm);

    float acc[2][NI][4];
    #pragma unroll
    for (int i = 0; i < 2; i++)
        #pragma unroll
        for (int j = 0; j < NI; j++)
            #pragma unroll
            for (int e = 0; e < 4; e++) acc[i][j][e] = 0.f;

    const int ar  = tid >> 1;
    const int as  = (tid & 1) * 2;

    const uint32_t aRow = lane & 15;
    const uint32_t aCol = (lane >> 4) * 8;
    const uint32_t aOff = (uint32_t)((mw + aRow) * ALD + aCol) * 2;
    const uint32_t bOff = (uint32_t)(A_PLANE + (lane & 15) * BLD + nw + (lane >> 4) * 8) * 2;

    auto load_stage = [&](int stg, int ch) {
        const uint32_t sb = sm_base + (uint32_t)stg * (STAGE_E * 2);
        const int k0 = ch * KCH;
        #pragma unroll
        for (int s = 0; s < 2; s++) {
            int seg = as + s;
            cp16(sb + (uint32_t)(ar * ALD + seg * 8) * 2,
                 A + (size_t)(m0 + ar) * lda + k0 + seg * 8);
        }
        #pragma unroll
        for (int s = 0; s < BSEG; s++) {
            int idx = tid * BSEG + s;
            int row = idx / (NTILE / 8);
            int seg = idx % (NTILE / 8);
            cp16(sb + (uint32_t)(A_PLANE + row * BLD + seg * 8) * 2,
                 B + (size_t)(k0 + row) * ldb + n0 + seg * 8);
        }
    };

    load_stage(0, 0);
    CP_COMMIT();

    for (int ch = 0; ch < nchunks; ch++) {
        const int stg = ch & 1;
        if (ch + 1 < nchunks) {
            load_stage(stg ^ 1, ch + 1);
            CP_COMMIT();
            CP_WAIT(1);
        } else {
            CP_WAIT(0);
        }
        __syncthreads();

        const uint32_t sb = sm_base + (uint32_t)stg * (STAGE_E * 2);
        #pragma unroll
        for (int ks = 0; ks < 2; ks++) {
            const uint32_t kA = (uint32_t)(ks * 16) * 2;
            const uint32_t kB = (uint32_t)(ks * 16 * BLD) * 2;
            uint32_t a[2][4], b[NI][2];
            #pragma unroll
            for (int mi = 0; mi < 2; mi++) {
                uint32_t off = (uint32_t)(mi * 16 * ALD) * 2 + kA;
                ldsm4(a[mi][0], a[mi][1], a[mi][2], a[mi][3], sb + aOff + off);
            }
            #pragma unroll
            for (int np = 0; np < NI / 2; np++) {
                uint32_t off = kB + (uint32_t)(np * 16) * 2;
                ldsm4t(b[np * 2][0], b[np * 2][1], b[np * 2 + 1][0], b[np * 2 + 1][1],
                       sb + bOff + off);
            }
            #pragma unroll
            for (int mi = 0; mi < 2; mi++)
                #pragma unroll
                for (int ni = 0; ni < NI; ni++)
                    mma16816(acc[mi][ni], a[mi], b[ni]);
        }
        __syncthreads();
    }

    const int cr = lane >> 2;
    const int cc = (lane & 3) * 2;
    #pragma unroll
    for (int mi = 0; mi < 2; mi++)
        #pragma unroll
        for (int ni = 0; ni < NI; ni++) {
            int row = m0 + mw + mi * 16 + cr;
            int col = n0 + nw + ni * 8 + cc;
            if (Cf) {
                *reinterpret_cast<float2*>(Cf + (size_t)row * ldc + col) =
                    make_float2(acc[mi][ni][0], acc[mi][ni][1]);
                *reinterpret_cast<float2*>(Cf + (size_t)(row + 8) * ldc + col) =
                    make_float2(acc[mi][ni][2], acc[mi][ni][3]);
            }
            if (Ch) {
                *reinterpret_cast<uint32_t*>(Ch + (size_t)row * ldh + col) =
                    pack_h2(acc[mi][ni][0], acc[mi][ni][1]);
                *reinterpret_cast<uint32_t*>(Ch + (size_t)(row + 8) * ldh + col) =
                    pack_h2(acc[mi][ni][2], acc[mi][ni][3]);
            }
        }
}

#define GEMM_SMEM_128 (2 * (A_PLANE + KCH * 136) * 2)
#define GEMM_SMEM_64  (2 * (A_PLANE + KCH * 72) * 2)

// ---------------- RoPE ----------------
__global__ void rope_kernel()
{
    const int row  = blockIdx.x;
    const int pos  = row & (SEQ - 1);
    const int warp = threadIdx.x >> 5;
    const int lane = threadIdx.x & 31;

    float theta = __powf(10000.0f, -(float)lane * (1.0f / 32.0f));
    float ang = (float)pos * theta;
    float s, c;
    sincosf(ang, &s, &c);

    if (warp < 16) {
        size_t off = (size_t)row * 3072 + warp * 192 + 128 + 2 * lane;
        uint32_t hv = *reinterpret_cast<uint32_t*>(g_qh + off);
        __half2 h2 = *reinterpret_cast<__half2*>(&hv);
        float x1 = __half2float(h2.x);
        float x2 = __half2float(h2.y);
        *reinterpret_cast<uint32_t*>(g_qh + off) =
            pack_h2(x1 * c - x2 * s, x1 * s + x2 * c);
    } else {
        size_t off = (size_t)row * 576 + 512 + 2 * lane;
        uint32_t hv = *reinterpret_cast<uint32_t*>(g_ckvh + off);
        __half2 h2 = *reinterpret_cast<__half2*>(&hv);
        float x1 = __half2float(h2.x);
        float x2 = __half2float(h2.y);
        *reinterpret_cast<uint32_t*>(g_peh + (size_t)row * 64 + 2 * lane) =
            pack_h2(x1 * c - x2 * s, x1 * s + x2 * c);
    }
}

// ================= HMMA fp16 flash attention, KT=64 =================
#define QT 128
#define KT 64
#define QLD 200
#define KLD 200
#define VLD 136
#define AQ 0
#define AK (QT * QLD)                        // 25600
#define K_STG (KT * KLD)                     // 12800
#define AV (AK + 2 * K_STG)                  // 51200
#define V_STG (KT * VLD)                     // 8704
#define ATT_E (AV + 2 * V_STG)               // 68608 elems
#define ATT_SMEM (ATT_E * 2)                 // 137216 bytes

__global__ __launch_bounds__(256, 1) void attn_hmma()
{
    extern __shared__ __half sm[];
    const int tid = threadIdx.x, wid = tid >> 5, lane = tid & 31;
    const int b = blockIdx.z, h = blockIdx.y;
    const int q0 = blockIdx.x * QT;
    const uint32_t sb = smem_u32(sm);
    const float scale = 0.07216878364870323f;   // 1/sqrt(192)

    // ---- async load Q tile [128][192] ----
    {
        int r = tid >> 1;
        const __half* src = g_qh + (size_t)(b * SEQ + q0 + r) * 3072 + h * 192;
        uint32_t dst = sb + (uint32_t)(AQ + r * QLD) * 2;
        #pragma unroll
        for (int s = 0; s < 12; s++) {
            int seg = (tid & 1) * 12 + s;
            cp16(dst + seg * 16, src + seg * 8);
        }
    }

    auto load_kv = [&](int stg, int kt0) {
        int r = tid >> 2;                     // 64 rows x 4 threads
        size_t row = (size_t)(b * SEQ + kt0 + r);
        const __half* kn = g_kvh + row * 4096 + h * 256;
        const __half* pe = g_peh + row * 64;
        uint32_t kd = sb + (uint32_t)(AK + stg * K_STG + r * KLD) * 2;
        uint32_t vd = sb + (uint32_t)(AV + stg * V_STG + r * VLD) * 2;
        #pragma unroll
        for (int s = 0; s < 10; s++) {
            int seg = (tid & 3) * 10 + s;
            if (seg < 16)      cp16(kd + seg * 16, kn + seg * 8);
            else if (seg < 24) cp16(kd + seg * 16, pe + (seg - 16) * 8);
            else               cp16(vd + (seg - 24) * 16, kn + 128 + (seg - 24) * 8);
        }
    };

    load_kv(0, 0);
    CP_COMMIT();

    const int ntiles = q0 / KT + QT / KT;
    float m0 = -INFINITY, m1 = -INFINITY, l0 = 0.f, l1 = 0.f;
    float O[16][4];
    #pragma unroll
    for (int od = 0; od < 16; od++)
        #pragma unroll
        for (int e = 0; e < 4; e++) O[od][e] = 0.f;

    const uint32_t qb = sb + (uint32_t)(AQ + (wid * 16 + (lane & 15)) * QLD + (lane >> 4) * 8) * 2;

    for (int t = 0; t < ntiles; t++) {
        const int stg = t & 1;
        if (t + 1 < ntiles) {
            load_kv(stg ^ 1, (t + 1) * KT);
            CP_COMMIT();
            CP_WAIT(1);
        } else {
            CP_WAIT(0);
        }
        __syncthreads();

        // ---- S = Q K^T : 8 n-frags (64 keys) ----
        float S[8][4];
        #pragma unroll
        for (int g = 0; g < 8; g++)
            #pragma unroll
            for (int e = 0; e < 4; e++) S[g][e] = 0.f;

        const uint32_t kb = sb + (uint32_t)(AK + stg * K_STG + (lane & 15) * KLD + (lane >> 4) * 8) * 2;
        #pragma unroll
        for (int ks = 0; ks < 12; ks++) {
            uint32_t a[4];
            ldsm4(a[0], a[1], a[2], a[3], qb + ks * 32);
            #pragma unroll
            for (int np = 0; np < 4; np++) {
                uint32_t off = (uint32_t)(np * 16 * KLD) * 2 + ks * 32;
                uint32_t h0, h1, h2, h3;
                ldsm4(h0, h1, h2, h3, kb + off);
                uint32_t b0[2] = {h0, h2}, b1[2] = {h1, h3};
                mma16816(S[np * 2],     a, b0);
                mma16816(S[np * 2 + 1], a, b1);
            }
        }

        // ---- scale + causal mask ----
        const int mrow0 = q0 + wid * 16 + (lane >> 2);
        const int kcol0 = t * KT + (lane & 3) * 2;
        const bool needmask = (t * KT + KT - 1) > (q0 + wid * 16);
        if (needmask) {
            #pragma unroll
            for (int g = 0; g < 8; g++) {
                int kc = kcol0 + g * 8;
                S[g][0] = (kc     <= mrow0)     ? S[g][0] * scale : -INFINITY;
                S[g][1] = (kc + 1 <= mrow0)     ? S[g][1] * scale : -INFINITY;
                S[g][2] = (kc     <= mrow0 + 8) ? S[g][2] * scale : -INFINITY;
                S[g][3] = (kc + 1 <= mrow0 + 8) ? S[g][3] * scale : -INFINITY;
            }
        } else {
            #pragma unroll
            for (int g = 0; g < 8; g++)
                #pragma unroll
                for (int e = 0; e < 4; e++) S[g][e] *= scale;
        }

        // ---- online softmax ----
        float tm0 = -INFINITY, tm1 = -INFINITY;
        #pragma unroll
        for (int g = 0; g < 8; g++) {
            tm0 = fmaxf(tm0, fmaxf(S[g][0], S[g][1]));
            tm1 = fmaxf(tm1, fmaxf(S[g][2], S[g][3]));
        }
        tm0 = fmaxf(tm0, __shfl_xor_sync(0xffffffffu, tm0, 1));
        tm0 = fmaxf(tm0, __shfl_xor_sync(0xffffffffu, tm0, 2));
        tm1 = fmaxf(tm1, __shfl_xor_sync(0xffffffffu, tm1, 1));
        tm1 = fmaxf(tm1, __shfl_xor_sync(0xffffffffu, tm1, 2));

        float mn0 = fmaxf(m0, tm0), mn1 = fmaxf(m1, tm1);
        float al0 = __expf(m0 - mn0), al1 = __expf(m1 - mn1);
        m0 = mn0; m1 = mn1;

        float P[8][4];
        float s0 = 0.f, s1 = 0.f;
        #pragma unroll
        for (int g = 0; g < 8; g++) {
            P[g][0] = __expf(S[g][0] - m0); s0 += P[g][0];
            P[g][1] = __expf(S[g][1] - m0); s0 += P[g][1];
            P[g][2] = __expf(S[g][2] - m1); s1 += P[g][2];
            P[g][3] = __expf(S[g][3] - m1); s1 += P[g][3];
        }
        s0 += __shfl_xor_sync(0xffffffffu, s0, 1);
        s0 += __shfl_xor_sync(0xffffffffu, s0, 2);
        s1 += __shfl_xor_sync(0xffffffffu, s1, 1);
        s1 += __shfl_xor_sync(0xffffffffu, s1, 2);
        l0 = l0 * al0 + s0;
        l1 = l1 * al1 + s1;

        #pragma unroll
        for (int od = 0; od < 16; od++) {
            O[od][0] *= al0; O[od][1] *= al0;
            O[od][2] *= al1; O[od][3] *= al1;
        }

        // ---- P -> fp16 a-frags (4 kp groups of 16 keys) ----
        uint32_t aP[4][4];
        #pragma unroll
        for (int kp = 0; kp < 4; kp++) {
            #pragma unroll
            for (int rr = 0; rr < 2; rr++) {
                #pragma unroll
                for (int hh = 0; hh < 2; hh++) {
                    aP[kp][hh * 2 + rr] = pack_h2(P[2 * kp + hh][rr * 2 + 0],
                                                  P[2 * kp + hh][rr * 2 + 1]);
                }
            }
        }

        // ---- O += P V ----
        const uint32_t vb = sb + (uint32_t)(AV + stg * V_STG + (lane & 15) * VLD + (lane >> 4) * 8) * 2;
        #pragma unroll
        for (int kp = 0; kp < 4; kp++) {
            const uint32_t vk = vb + (uint32_t)(kp * 16 * VLD) * 2;
            #pragma unroll
            for (int od2 = 0; od2 < 8; od2++) {
                uint32_t bv[4];
                ldsm4t(bv[0], bv[1], bv[2], bv[3], vk + od2 * 32);
                mma16816(O[od2 * 2],     aP[kp], bv);
                mma16816(O[od2 * 2 + 1], aP[kp], bv + 2);
            }
        }
        __syncthreads();
    }

    // ---- normalize + fp16 write ----
    float inv0 = 1.f / l0, inv1 = 1.f / l1;
    int row0 = b * SEQ + q0 + wid * 16 + (lane >> 2);
    size_t o0 = (size_t)row0 * 2048 + h * 128 + (lane & 3) * 2;
    size_t o1 = (size_t)(row0 + 8) * 2048 + h * 128 + (lane & 3) * 2;
    #pragma unroll
    for (int od = 0; od < 16; od++) {
        *reinterpret_cast<uint32_t*>(g_ah + o0 + od * 8) =
            pack_h2(O[od][0] * inv0, O[od][1] * inv0);
        *reinterpret_cast<uint32_t*>(g_ah + o1 + od * 8) =
            pack_h2(O[od][2] * inv1, O[od][3] * inv1);
    }
}

// ---------------- launch ----------------
static inline void conv(const float* in, __half* out, int nelem)
{
    int n4 = nelem / 4;
    conv_h<<<(n4 + 255) / 256, 256>>>(in, out, n4);
}

extern "C" void kernel_launch(void* const* d_in, const int* in_sizes, int n_in,
                              void* d_out, int out_size)
{
    const float* x    = (const float*)d_in[0];
    const float* Wqa  = (const float*)d_in[1];
    const float* Wqb  = (const float*)d_in[2];
    const float* Wkva = (const float*)d_in[3];
    const float* Wkvb = (const float*)d_in[4];
    const float* Wout = (const float*)d_in[5];
    float* out = (float*)d_out;

    __half *xh, *q1h, *ckvh, *qh, *kvh, *ah;
    __half *wqah, *wqbh, *wkvah, *wkvbh, *wouth;
    cudaGetSymbolAddress((void**)&xh,   g_xh);
    cudaGetSymbolAddress((void**)&q1h,  g_q1h);
    cudaGetSymbolAddress((void**)&ckvh, g_ckvh);
    cudaGetSymbolAddress((void**)&qh,   g_qh);
    cudaGetSymbolAddress((void**)&kvh,  g_kvh);
    cudaGetSymbolAddress((void**)&ah,   g_ah);
    cudaGetSymbolAddress((void**)&wqah, g_Wqah);
    cudaGetSymbolAddress((void**)&wqbh, g_Wqbh);
    cudaGetSymbolAddress((void**)&wkvah, g_Wkvah);
    cudaGetSymbolAddress((void**)&wkvbh, g_Wkvbh);
    cudaGetSymbolAddress((void**)&wouth, g_Wouth);

    cudaFuncSetAttribute(gemm_hmma<128>,
                         cudaFuncAttributeMaxDynamicSharedMemorySize, GEMM_SMEM_128);
    cudaFuncSetAttribute(gemm_hmma<64>,
                         cudaFuncAttributeMaxDynamicSharedMemorySize, GEMM_SMEM_64);
    cudaFuncSetAttribute(attn_hmma,
                         cudaFuncAttributeMaxDynamicSharedMemorySize, ATT_SMEM);

    // ---- input conversions ----
    conv(x,    xh,    NROWS * 2048);
    conv(Wqa,  wqah,  2048 * 512);
    conv(Wqb,  wqbh,  512 * 3072);
    conv(Wkva, wkvah, 2048 * 576);
    conv(Wkvb, wkvbh, 512 * 4096);
    conv(Wout, wouth, 2048 * 2048);

    dim3 t(256);
    // q1 = x @ Wqa -> fp16
    gemm_hmma<128><<<dim3(4, 32),  t, GEMM_SMEM_128>>>(xh, 2048, wqah, 512,
                                                       nullptr, 0, q1h, 512, 64);
    // q = q1 @ Wqb -> fp16
    gemm_hmma<128><<<dim3(24, 32), t, GEMM_SMEM_128>>>(q1h, 512, wqbh, 3072,
                                                       nullptr, 0, qh, 3072, 16);
    // ckv = x @ Wkva -> fp16 (cols 0..511 wide tile, 512..575 narrow tile)
    gemm_hmma<128><<<dim3(4, 32),  t, GEMM_SMEM_128>>>(xh, 2048, wkvah, 576,
                                                       nullptr, 0, ckvh, 576, 64);
    gemm_hmma<64><<<dim3(1, 32),   t, GEMM_SMEM_64>>>(xh, 2048, wkvah + 512, 576,
                                                      nullptr, 0, ckvh + 512, 576, 64);
    // rope (q_pe in place; k_pe -> pe plane)
    rope_kernel<<<4096, 544>>>();
    // kv = ckv[:, :512] @ Wkvb -> fp16
    gemm_hmma<128><<<dim3(32, 32), t, GEMM_SMEM_128>>>(ckvh, 576, wkvbh, 4096,
                                                       nullptr, 0, kvh, 4096, 16);
    // flash attention -> fp16
    attn_hmma<<<dim3(SEQ / QT, NHEADS, 2), 256, ATT_SMEM>>>();
    // out = att @ Wout -> fp32
    gemm_hmma<128><<<dim3(16, 32), t, GEMM_SMEM_128>>>(ah, 2048, wouth, 2048,
                                                       out, 2048, nullptr, 0, 64);
}